// round 1
// baseline (speedup 1.0000x reference)
#include <cuda_runtime.h>
#include <math.h>

#define N_NODES 50000
#define N_EDGES 800000
#define DH 128
#define DOUT 64

// ---------------- scratch (device globals: no allocation allowed) ----------------
__device__ float g_m1[N_NODES * DH];
__device__ float g_q1[N_NODES * DH];
__device__ float g_p1[N_NODES * DH];
__device__ float g_m2[N_NODES * DH];
__device__ float g_q2[N_NODES * DOUT];
__device__ float g_p2[N_NODES * DOUT];
__device__ int   g_cnt[N_NODES];
__device__ int   g_fill[N_NODES];
__device__ int   g_rowptr[N_NODES + 1];
__device__ int   g_csrc[N_EDGES];

// ---------------- helpers ----------------
__device__ __forceinline__ float gelu_erf(float x) {
    return 0.5f * x * (1.0f + erff(x * 0.70710678118654752440f));
}

__device__ __forceinline__ unsigned long long bcast2(float x) {
    unsigned long long r;
    unsigned int b = __float_as_uint(x);
    asm("mov.b64 %0, {%1, %1};" : "=l"(r) : "r"(b));
    return r;
}

__device__ __forceinline__ void fma2(unsigned long long& d, unsigned long long a,
                                     unsigned long long b) {
    asm("fma.rn.f32x2 %0, %1, %2, %0;" : "+l"(d) : "l"(a), "l"(b));
}

// ---------------- CSR build ----------------
__global__ void k_zero() {
    int i = blockIdx.x * blockDim.x + threadIdx.x;
    if (i < N_NODES) { g_cnt[i] = 0; g_fill[i] = 0; }
}

__global__ void k_hist(const int* __restrict__ dst) {
    int e = blockIdx.x * blockDim.x + threadIdx.x;
    if (e < N_EDGES) atomicAdd(&g_cnt[dst[e]], 1);
}

__global__ void k_scan() {
    // single block, 1024 threads, exclusive scan of g_cnt -> g_rowptr
    const int NT = 1024;
    const int C = (N_NODES + NT - 1) / NT;  // 49
    int t = threadIdx.x;
    int beg = t * C;
    int end = min(N_NODES, beg + C);
    int s = 0;
    for (int i = beg; i < end; i++) s += g_cnt[i];
    __shared__ int sums[NT];
    sums[t] = s;
    __syncthreads();
    for (int off = 1; off < NT; off <<= 1) {
        int v = (t >= off) ? sums[t - off] : 0;
        __syncthreads();
        sums[t] += v;
        __syncthreads();
    }
    int run = (t == 0) ? 0 : sums[t - 1];
    for (int i = beg; i < end; i++) {
        g_rowptr[i] = run;
        run += g_cnt[i];
    }
    if (t == 0) g_rowptr[N_NODES] = N_EDGES;
}

__global__ void k_scatter(const int* __restrict__ src, const int* __restrict__ dst) {
    int e = blockIdx.x * blockDim.x + threadIdx.x;
    if (e < N_EDGES) {
        int d = dst[e];
        int pos = g_rowptr[d] + atomicAdd(&g_fill[d], 1);
        g_csrc[pos] = src[e];
    }
}

// ---------------- GEMM: C[M,NO] = act(A[M,128] @ W[128,NO] + bias) ----------------
// BM=64 rows per block, 256 threads (16x16), packed f32x2 FMA inner loop.
template <int NO, bool ACT_GELU>
__global__ __launch_bounds__(256) void gemm_k128(const float* __restrict__ A,
                                                 const float* __restrict__ W,
                                                 const float* __restrict__ bias,
                                                 float* __restrict__ C, int M) {
    constexpr int BM = 64, BK = 32;
    constexpr int CPT = NO / 16;   // cols per thread: 8 (NO=128) or 4 (NO=64)
    constexpr int CP2 = CPT / 2;   // f32x2 pairs per thread: 4 or 2
    __shared__ float sA[BK][BM + 4];   // transposed: sA[k][row]
    __shared__ float sW[BK][NO + 4];

    const int tid = threadIdx.x;
    const int tx = tid & 15;
    const int ty = tid >> 4;
    const int row0 = blockIdx.x * BM;

    unsigned long long acc[4][CP2];
#pragma unroll
    for (int r = 0; r < 4; r++)
#pragma unroll
        for (int c = 0; c < CP2; c++) acc[r][c] = 0ULL;

    for (int k0 = 0; k0 < 128; k0 += BK) {
        // load A tile (64 x 32), transposed into sA
#pragma unroll
        for (int i = 0; i < 2; i++) {
            int f = tid * 2 + i;
            int r = f >> 3;
            int cv = f & 7;
            float4 v = make_float4(0.f, 0.f, 0.f, 0.f);
            if (row0 + r < M)
                v = *(const float4*)(A + (size_t)(row0 + r) * 128 + k0 + cv * 4);
            sA[cv * 4 + 0][r] = v.x;
            sA[cv * 4 + 1][r] = v.y;
            sA[cv * 4 + 2][r] = v.z;
            sA[cv * 4 + 3][r] = v.w;
        }
        // load W tile (32 x NO)
        constexpr int WV = (BK * NO) / (256 * 4);
#pragma unroll
        for (int i = 0; i < WV; i++) {
            int f = tid + i * 256;
            int r = f / (NO / 4);
            int c4 = f % (NO / 4);
            float4 v = *(const float4*)(W + (size_t)(k0 + r) * NO + c4 * 4);
            *(float4*)&sW[r][c4 * 4] = v;
        }
        __syncthreads();
#pragma unroll
        for (int kk = 0; kk < BK; kk++) {
            float4 a4 = *(const float4*)&sA[kk][ty * 4];
            unsigned long long aa0 = bcast2(a4.x);
            unsigned long long aa1 = bcast2(a4.y);
            unsigned long long aa2 = bcast2(a4.z);
            unsigned long long aa3 = bcast2(a4.w);
            unsigned long long wp[CP2];
#pragma unroll
            for (int c = 0; c < CP2; c += 2) {
                ulonglong2 wv = *(const ulonglong2*)&sW[kk][tx * CPT + c * 2];
                wp[c] = wv.x;
                wp[c + 1] = wv.y;
            }
#pragma unroll
            for (int c = 0; c < CP2; c++) {
                fma2(acc[0][c], aa0, wp[c]);
                fma2(acc[1][c], aa1, wp[c]);
                fma2(acc[2][c], aa2, wp[c]);
                fma2(acc[3][c], aa3, wp[c]);
            }
        }
        __syncthreads();
    }
    // epilogue
#pragma unroll
    for (int r = 0; r < 4; r++) {
        int row = row0 + ty * 4 + r;
        if (row < M) {
#pragma unroll
            for (int c = 0; c < CP2; c++) {
                union { unsigned long long u; float2 f; } u;
                u.u = acc[r][c];
                int col = tx * CPT + c * 2;
                float o0 = u.f.x + bias[col];
                float o1 = u.f.y + bias[col + 1];
                if (ACT_GELU) { o0 = gelu_erf(o0); o1 = gelu_erf(o1); }
                C[(size_t)row * NO + col] = o0;
                C[(size_t)row * NO + col + 1] = o1;
            }
        }
    }
}

// ---------------- GAT block, D=128: one warp per dst node -----------------------
// agg[n] = (sum_e es_e * p[src_e]) / (sum_e es_e);  out = gelu(agg + badd)
__global__ __launch_bounds__(256) void k_gat128(const float* __restrict__ q,
                                                const float* __restrict__ p,
                                                const float* __restrict__ avec,
                                                const float* __restrict__ badd,
                                                float* __restrict__ out) {
    int w = (blockIdx.x * blockDim.x + threadIdx.x) >> 5;
    int lane = threadIdx.x & 31;
    if (w >= N_NODES) return;
    const float4* p4 = (const float4*)p;
    float4 qv = ((const float4*)q)[(size_t)w * 32 + lane];
    float4 av = ((const float4*)avec)[lane];
    int beg = g_rowptr[w];
    int end = g_rowptr[w + 1];
    float denom = 0.f;
    float ax = 0.f, ay = 0.f, az = 0.f, aw = 0.f;
    for (int pos = beg; pos < end; ++pos) {
        int s = g_csrc[pos];
        float4 pv = p4[(size_t)s * 32 + lane];
        float d0 = qv.x + pv.x; d0 = (d0 > 0.f) ? d0 : 0.2f * d0;
        float d1 = qv.y + pv.y; d1 = (d1 > 0.f) ? d1 : 0.2f * d1;
        float d2 = qv.z + pv.z; d2 = (d2 > 0.f) ? d2 : 0.2f * d2;
        float d3 = qv.w + pv.w; d3 = (d3 > 0.f) ? d3 : 0.2f * d3;
        float partial = d0 * av.x + d1 * av.y + d2 * av.z + d3 * av.w;
#pragma unroll
        for (int o = 16; o; o >>= 1) partial += __shfl_xor_sync(0xffffffffu, partial, o);
        float es = expf(partial);
        denom += es;
        ax = fmaf(es, pv.x, ax);
        ay = fmaf(es, pv.y, ay);
        az = fmaf(es, pv.z, az);
        aw = fmaf(es, pv.w, aw);
    }
    float inv = (end > beg) ? 1.f / denom : 0.f;
    int col = lane * 4;
    float4 o;
    o.x = gelu_erf(fmaf(ax, inv, badd[col + 0]));
    o.y = gelu_erf(fmaf(ay, inv, badd[col + 1]));
    o.z = gelu_erf(fmaf(az, inv, badd[col + 2]));
    o.w = gelu_erf(fmaf(aw, inv, badd[col + 3]));
    ((float4*)out)[(size_t)w * 32 + lane] = o;
}

// ---------------- GAT block, D=64: one warp per dst node; out = agg + b_out -----
__global__ __launch_bounds__(256) void k_gat64(const float* __restrict__ q,
                                               const float* __restrict__ p,
                                               const float* __restrict__ avec,
                                               const float* __restrict__ bout,
                                               float* __restrict__ out) {
    int w = (blockIdx.x * blockDim.x + threadIdx.x) >> 5;
    int lane = threadIdx.x & 31;
    if (w >= N_NODES) return;
    const float2* p2 = (const float2*)p;
    float2 qv = ((const float2*)q)[(size_t)w * 32 + lane];
    float2 av = ((const float2*)avec)[lane];
    int beg = g_rowptr[w];
    int end = g_rowptr[w + 1];
    float denom = 0.f;
    float ax = 0.f, ay = 0.f;
    for (int pos = beg; pos < end; ++pos) {
        int s = g_csrc[pos];
        float2 pv = p2[(size_t)s * 32 + lane];
        float d0 = qv.x + pv.x; d0 = (d0 > 0.f) ? d0 : 0.2f * d0;
        float d1 = qv.y + pv.y; d1 = (d1 > 0.f) ? d1 : 0.2f * d1;
        float partial = d0 * av.x + d1 * av.y;
#pragma unroll
        for (int o = 16; o; o >>= 1) partial += __shfl_xor_sync(0xffffffffu, partial, o);
        float es = expf(partial);
        denom += es;
        ax = fmaf(es, pv.x, ax);
        ay = fmaf(es, pv.y, ay);
    }
    float inv = (end > beg) ? 1.f / denom : 0.f;
    int col = lane * 2;
    float2 o;
    o.x = fmaf(ax, inv, bout[col + 0]);
    o.y = fmaf(ay, inv, bout[col + 1]);
    ((float2*)out)[(size_t)w * 32 + lane] = o;
}

// ---------------- launch ----------------
extern "C" void kernel_launch(void* const* d_in, const int* in_sizes, int n_in,
                              void* d_out, int out_size) {
    const float* x    = (const float*)d_in[0];
    const float* W0   = (const float*)d_in[1];
    const float* b0   = (const float*)d_in[2];
    const float* Wq1  = (const float*)d_in[3];
    const float* bq1  = (const float*)d_in[4];
    const float* Wp1  = (const float*)d_in[5];
    const float* bp1  = (const float*)d_in[6];
    const float* a1   = (const float*)d_in[7];
    const float* bg2  = (const float*)d_in[8];
    const float* Wq2  = (const float*)d_in[9];
    const float* bq2  = (const float*)d_in[10];
    const float* Wp2  = (const float*)d_in[11];
    const float* bp2  = (const float*)d_in[12];
    const float* a2   = (const float*)d_in[13];
    const float* b_out= (const float*)d_in[14];
    const int*   src  = (const int*)d_in[15];
    const int*   dst  = (const int*)d_in[16];

    float *m1, *q1, *p1, *m2, *q2, *p2;
    cudaGetSymbolAddress((void**)&m1, g_m1);
    cudaGetSymbolAddress((void**)&q1, g_q1);
    cudaGetSymbolAddress((void**)&p1, g_p1);
    cudaGetSymbolAddress((void**)&m2, g_m2);
    cudaGetSymbolAddress((void**)&q2, g_q2);
    cudaGetSymbolAddress((void**)&p2, g_p2);

    const int gemm_grid = (N_NODES + 63) / 64;        // 782
    const int gat_grid  = (N_NODES + 7) / 8;          // 6250 (8 warps/block)

    // CSR build (per replay; deterministic up to fp-accumulation order)
    k_zero<<<(N_NODES + 255) / 256, 256>>>();
    k_hist<<<(N_EDGES + 255) / 256, 256>>>(dst);
    k_scan<<<1, 1024>>>();
    k_scatter<<<(N_EDGES + 255) / 256, 256>>>(src, dst);

    // layer 1
    gemm_k128<128, true ><<<gemm_grid, 256>>>(x,  W0,  b0,  m1, N_NODES);
    gemm_k128<128, false><<<gemm_grid, 256>>>(m1, Wq1, bq1, q1, N_NODES);
    gemm_k128<128, false><<<gemm_grid, 256>>>(m1, Wp1, bp1, p1, N_NODES);
    k_gat128<<<gat_grid, 256>>>(q1, p1, a1, bg2, m2);   // fuses +bg2 and gelu

    // layer 2
    gemm_k128<64, false><<<gemm_grid, 256>>>(m2, Wq2, bq2, q2, N_NODES);
    gemm_k128<64, false><<<gemm_grid, 256>>>(m2, Wp2, bp2, p2, N_NODES);
    k_gat64<<<gat_grid, 256>>>(q2, p2, a2, b_out, (float*)d_out);  // fuses +b_out
}

// round 3
// speedup vs baseline: 1.4043x; 1.4043x over previous
#include <cuda_runtime.h>
#include <cuda_bf16.h>
#include <math.h>
#include <stdint.h>

#define N_NODES 50000
#define N_EDGES 800000
#define DH 128
#define DOUT 64

// ---------------- scratch (device globals: no allocation allowed) ----------------
__device__ float g_m1[N_NODES * DH];
__device__ float g_q1[N_NODES * DH];
__device__ float g_p1[N_NODES * DH];
__device__ float g_m2[N_NODES * DH];
__device__ float g_q2[N_NODES * DOUT];
__device__ float g_p2[N_NODES * DOUT];
__device__ int   g_cnt[N_NODES];
__device__ int   g_fill[N_NODES];
__device__ int   g_rowptr[N_NODES + 1];
__device__ int   g_csrc[N_EDGES];

// bf16 hi/lo split weights, plain row-major [K][NO]
__device__ __nv_bfloat16 g_w0h[128 * 128], g_w0l[128 * 128];
__device__ __nv_bfloat16 g_wq1h[128 * 128], g_wq1l[128 * 128];
__device__ __nv_bfloat16 g_wp1h[128 * 128], g_wp1l[128 * 128];
__device__ __nv_bfloat16 g_wq2h[128 * 64], g_wq2l[128 * 64];
__device__ __nv_bfloat16 g_wp2h[128 * 64], g_wp2l[128 * 64];

// ---------------- helpers ----------------
__device__ __forceinline__ float gelu_erf(float x) {
    return 0.5f * x * (1.0f + erff(x * 0.70710678118654752440f));
}

__device__ __forceinline__ uint32_t smem_u32(const void* p) {
    uint32_t a;
    asm("{ .reg .u64 t; cvta.to.shared.u64 t, %1; cvt.u32.u64 %0, t; }" : "=r"(a) : "l"(p));
    return a;
}

__device__ __forceinline__ void ldx4(uint32_t* r, uint32_t addr) {
    asm volatile("ldmatrix.sync.aligned.m8n8.x4.shared.b16 {%0,%1,%2,%3}, [%4];"
                 : "=r"(r[0]), "=r"(r[1]), "=r"(r[2]), "=r"(r[3]) : "r"(addr));
}

__device__ __forceinline__ void ldx4t(uint32_t* r, uint32_t addr) {
    asm volatile("ldmatrix.sync.aligned.m8n8.x4.trans.shared.b16 {%0,%1,%2,%3}, [%4];"
                 : "=r"(r[0]), "=r"(r[1]), "=r"(r[2]), "=r"(r[3]) : "r"(addr));
}

__device__ __forceinline__ void mma16816(float* c, const uint32_t* a, uint32_t b0, uint32_t b1) {
    asm volatile(
        "mma.sync.aligned.m16n8k16.row.col.f32.bf16.bf16.f32 "
        "{%0,%1,%2,%3}, {%4,%5,%6,%7}, {%8,%9}, {%0,%1,%2,%3};"
        : "+f"(c[0]), "+f"(c[1]), "+f"(c[2]), "+f"(c[3])
        : "r"(a[0]), "r"(a[1]), "r"(a[2]), "r"(a[3]), "r"(b0), "r"(b1));
}

__device__ __forceinline__ void split2(float a, float b, uint32_t& hi, uint32_t& lo) {
    __nv_bfloat16 ha = __float2bfloat16(a), hb = __float2bfloat16(b);
    __nv_bfloat16 la = __float2bfloat16(a - __bfloat162float(ha));
    __nv_bfloat16 lb = __float2bfloat16(b - __bfloat162float(hb));
    hi = (uint32_t)__bfloat16_as_ushort(ha) | ((uint32_t)__bfloat16_as_ushort(hb) << 16);
    lo = (uint32_t)__bfloat16_as_ushort(la) | ((uint32_t)__bfloat16_as_ushort(lb) << 16);
}

// ---------------- weight prep: fp32 -> bf16 hi/lo, same layout ----------------
__global__ void k_prep(const float* __restrict__ W, int n,
                       __nv_bfloat16* __restrict__ hi, __nv_bfloat16* __restrict__ lo) {
    int i = blockIdx.x * blockDim.x + threadIdx.x;
    if (i < n) {
        float v = W[i];
        __nv_bfloat16 h = __float2bfloat16(v);
        hi[i] = h;
        lo[i] = __float2bfloat16(v - __bfloat162float(h));
    }
}

// ---------------- mma.sync GEMM: C = act(A[M,128] @ W[128,NO] + bias) ----------------
// 256 threads = 8 warps (4m x 2n); warp tile 32 x NO/2; K chunked by 32.
template <int NO, bool ACT>
__global__ __launch_bounds__(256, 2) void k_gemm_mma(
    const float* __restrict__ A, const __nv_bfloat16* __restrict__ Wh,
    const __nv_bfloat16* __restrict__ Wl, const float* __restrict__ bias,
    float* __restrict__ C, int M) {
    constexpr int AP = 40;        // A smem row length (32 k + 8 pad)
    constexpr int WPAD = NO + 8;  // W smem row length
    constexpr int NB = NO / 16;   // 8-wide n-blocks per warp

    __shared__ alignas(16) __nv_bfloat16 sAh[128 * AP];
    __shared__ alignas(16) __nv_bfloat16 sAl[128 * AP];
    __shared__ alignas(16) __nv_bfloat16 sWh[32 * WPAD];
    __shared__ alignas(16) __nv_bfloat16 sWl[32 * WPAD];

    const int tid = threadIdx.x;
    const int wid = tid >> 5, lane = tid & 31;
    const int wm = wid & 3, wn = wid >> 2;
    const int row0 = blockIdx.x * 128;

    float acc[2][NB][4];
#pragma unroll
    for (int mb = 0; mb < 2; mb++)
#pragma unroll
        for (int nb = 0; nb < NB; nb++)
#pragma unroll
            for (int j = 0; j < 4; j++) acc[mb][nb][j] = 0.f;

    const uint32_t aBaseH = smem_u32(sAh), aBaseL = smem_u32(sAl);
    const uint32_t wBaseH = smem_u32(sWh), wBaseL = smem_u32(sWl);

    // ldmatrix address components
    const int a_row = wm * 32 + (lane & 15);
    const int a_col = (lane >> 4) * 8;
    const int b_blk = lane >> 3;
    const int b_rowoff = (b_blk & 1) * 8 + (lane & 7);
    const int b_coladd = wn * (NO / 2) + (b_blk >> 1) * 8;

    for (int c = 0; c < 4; c++) {
        const int k0 = c * 32;
        // load + convert A chunk: 128 rows x 32 k
        for (int i = tid; i < 128 * 8; i += 256) {
            int r = i >> 3, q = i & 7;
            int grow = row0 + r;
            float4 v = make_float4(0.f, 0.f, 0.f, 0.f);
            if (grow < M) v = *(const float4*)(A + (size_t)grow * 128 + k0 + q * 4);
            uint32_t h0, l0, h1, l1;
            split2(v.x, v.y, h0, l0);
            split2(v.z, v.w, h1, l1);
            *(uint2*)(sAh + r * AP + q * 4) = make_uint2(h0, h1);
            *(uint2*)(sAl + r * AP + q * 4) = make_uint2(l0, l1);
        }
        // load W chunk: 32 k-rows x NO
        for (int i = tid; i < 32 * NO / 8; i += 256) {
            int r = i / (NO / 8), off = (i % (NO / 8)) * 8;
            *(uint4*)(sWh + r * WPAD + off) = *(const uint4*)(Wh + (size_t)(k0 + r) * NO + off);
            *(uint4*)(sWl + r * WPAD + off) = *(const uint4*)(Wl + (size_t)(k0 + r) * NO + off);
        }
        __syncthreads();

#pragma unroll
        for (int kc = 0; kc < 32; kc += 16) {
            uint32_t ah[2][4], al[2][4];
#pragma unroll
            for (int mb = 0; mb < 2; mb++) {
                uint32_t off = (uint32_t)((a_row + mb * 16) * AP + kc + a_col) * 2;
                ldx4(ah[mb], aBaseH + off);
                ldx4(al[mb], aBaseL + off);
            }
#pragma unroll
            for (int nb = 0; nb < NB; nb += 2) {
                uint32_t bh[4], bl[4];
                uint32_t off = (uint32_t)((kc + b_rowoff) * WPAD + nb * 8 + b_coladd) * 2;
                ldx4t(bh, wBaseH + off);
                ldx4t(bl, wBaseL + off);
#pragma unroll
                for (int mb = 0; mb < 2; mb++) {
                    mma16816(acc[mb][nb], ah[mb], bh[0], bh[1]);
                    mma16816(acc[mb][nb + 1], ah[mb], bh[2], bh[3]);
                    mma16816(acc[mb][nb], ah[mb], bl[0], bl[1]);
                    mma16816(acc[mb][nb + 1], ah[mb], bl[2], bl[3]);
                    mma16816(acc[mb][nb], al[mb], bh[0], bh[1]);
                    mma16816(acc[mb][nb + 1], al[mb], bh[2], bh[3]);
                }
            }
        }
        __syncthreads();
    }

    // epilogue
#pragma unroll
    for (int mb = 0; mb < 2; mb++) {
#pragma unroll
        for (int nb = 0; nb < NB; nb++) {
            int col = wn * (NO / 2) + nb * 8 + (lane & 3) * 2;
            float b0 = bias[col], b1 = bias[col + 1];
#pragma unroll
            for (int half = 0; half < 2; half++) {
                int r = row0 + wm * 32 + mb * 16 + (lane >> 2) + half * 8;
                if (r < M) {
                    float o0 = acc[mb][nb][half * 2 + 0] + b0;
                    float o1 = acc[mb][nb][half * 2 + 1] + b1;
                    if (ACT) { o0 = gelu_erf(o0); o1 = gelu_erf(o1); }
                    *(float2*)(C + (size_t)r * NO + col) = make_float2(o0, o1);
                }
            }
        }
    }
}

// ---------------- CSR build ----------------
__global__ void k_zero() {
    int i = blockIdx.x * blockDim.x + threadIdx.x;
    if (i < N_NODES) { g_cnt[i] = 0; g_fill[i] = 0; }
}

__global__ void k_hist(const int* __restrict__ dst) {
    int e = blockIdx.x * blockDim.x + threadIdx.x;
    if (e < N_EDGES) atomicAdd(&g_cnt[dst[e]], 1);
}

__global__ void k_scan() {
    const int NT = 1024;
    const int C = (N_NODES + NT - 1) / NT;
    int t = threadIdx.x;
    int beg = t * C;
    int end = min(N_NODES, beg + C);
    int s = 0;
    for (int i = beg; i < end; i++) s += g_cnt[i];
    __shared__ int sums[NT];
    sums[t] = s;
    __syncthreads();
    for (int off = 1; off < NT; off <<= 1) {
        int v = (t >= off) ? sums[t - off] : 0;
        __syncthreads();
        sums[t] += v;
        __syncthreads();
    }
    int run = (t == 0) ? 0 : sums[t - 1];
    for (int i = beg; i < end; i++) {
        g_rowptr[i] = run;
        run += g_cnt[i];
    }
    if (t == 0) g_rowptr[N_NODES] = N_EDGES;
}

__global__ void k_scatter(const int* __restrict__ src, const int* __restrict__ dst) {
    int e = blockIdx.x * blockDim.x + threadIdx.x;
    if (e < N_EDGES) {
        int d = dst[e];
        int pos = g_rowptr[d] + atomicAdd(&g_fill[d], 1);
        g_csrc[pos] = src[e];
    }
}

// ---------------- GAT block, D=128: one warp per dst node -----------------------
__global__ __launch_bounds__(256) void k_gat128(const float* __restrict__ q,
                                                const float* __restrict__ p,
                                                const float* __restrict__ avec,
                                                const float* __restrict__ badd,
                                                float* __restrict__ out) {
    int w = (blockIdx.x * blockDim.x + threadIdx.x) >> 5;
    int lane = threadIdx.x & 31;
    if (w >= N_NODES) return;
    const float4* p4 = (const float4*)p;
    float4 qv = ((const float4*)q)[(size_t)w * 32 + lane];
    float4 av = ((const float4*)avec)[lane];
    int beg = g_rowptr[w];
    int end = g_rowptr[w + 1];
    float denom = 0.f;
    float ax = 0.f, ay = 0.f, az = 0.f, aw = 0.f;
    for (int pos = beg; pos < end; ++pos) {
        int s = g_csrc[pos];
        float4 pv = p4[(size_t)s * 32 + lane];
        float d0 = qv.x + pv.x; d0 = (d0 > 0.f) ? d0 : 0.2f * d0;
        float d1 = qv.y + pv.y; d1 = (d1 > 0.f) ? d1 : 0.2f * d1;
        float d2 = qv.z + pv.z; d2 = (d2 > 0.f) ? d2 : 0.2f * d2;
        float d3 = qv.w + pv.w; d3 = (d3 > 0.f) ? d3 : 0.2f * d3;
        float partial = d0 * av.x + d1 * av.y + d2 * av.z + d3 * av.w;
#pragma unroll
        for (int o = 16; o; o >>= 1) partial += __shfl_xor_sync(0xffffffffu, partial, o);
        float es = expf(partial);
        denom += es;
        ax = fmaf(es, pv.x, ax);
        ay = fmaf(es, pv.y, ay);
        az = fmaf(es, pv.z, az);
        aw = fmaf(es, pv.w, aw);
    }
    float inv = (end > beg) ? 1.f / denom : 0.f;
    int col = lane * 4;
    float4 o;
    o.x = gelu_erf(fmaf(ax, inv, badd[col + 0]));
    o.y = gelu_erf(fmaf(ay, inv, badd[col + 1]));
    o.z = gelu_erf(fmaf(az, inv, badd[col + 2]));
    o.w = gelu_erf(fmaf(aw, inv, badd[col + 3]));
    ((float4*)out)[(size_t)w * 32 + lane] = o;
}

// ---------------- GAT block, D=64 ----------------
__global__ __launch_bounds__(256) void k_gat64(const float* __restrict__ q,
                                               const float* __restrict__ p,
                                               const float* __restrict__ avec,
                                               const float* __restrict__ bout,
                                               float* __restrict__ out) {
    int w = (blockIdx.x * blockDim.x + threadIdx.x) >> 5;
    int lane = threadIdx.x & 31;
    if (w >= N_NODES) return;
    const float2* p2 = (const float2*)p;
    float2 qv = ((const float2*)q)[(size_t)w * 32 + lane];
    float2 av = ((const float2*)avec)[lane];
    int beg = g_rowptr[w];
    int end = g_rowptr[w + 1];
    float denom = 0.f;
    float ax = 0.f, ay = 0.f;
    for (int pos = beg; pos < end; ++pos) {
        int s = g_csrc[pos];
        float2 pv = p2[(size_t)s * 32 + lane];
        float d0 = qv.x + pv.x; d0 = (d0 > 0.f) ? d0 : 0.2f * d0;
        float d1 = qv.y + pv.y; d1 = (d1 > 0.f) ? d1 : 0.2f * d1;
        float partial = d0 * av.x + d1 * av.y;
#pragma unroll
        for (int o = 16; o; o >>= 1) partial += __shfl_xor_sync(0xffffffffu, partial, o);
        float es = expf(partial);
        denom += es;
        ax = fmaf(es, pv.x, ax);
        ay = fmaf(es, pv.y, ay);
    }
    float inv = (end > beg) ? 1.f / denom : 0.f;
    int col = lane * 2;
    float2 o;
    o.x = fmaf(ax, inv, bout[col + 0]);
    o.y = fmaf(ay, inv, bout[col + 1]);
    ((float2*)out)[(size_t)w * 32 + lane] = o;
}

// ---------------- launch ----------------
extern "C" void kernel_launch(void* const* d_in, const int* in_sizes, int n_in,
                              void* d_out, int out_size) {
    const float* x    = (const float*)d_in[0];
    const float* W0   = (const float*)d_in[1];
    const float* b0   = (const float*)d_in[2];
    const float* Wq1  = (const float*)d_in[3];
    const float* bq1  = (const float*)d_in[4];
    const float* Wp1  = (const float*)d_in[5];
    const float* bp1  = (const float*)d_in[6];
    const float* a1   = (const float*)d_in[7];
    const float* bg2  = (const float*)d_in[8];
    const float* Wq2  = (const float*)d_in[9];
    const float* bq2  = (const float*)d_in[10];
    const float* Wp2  = (const float*)d_in[11];
    const float* bp2  = (const float*)d_in[12];
    const float* a2   = (const float*)d_in[13];
    const float* b_out= (const float*)d_in[14];
    const int*   src  = (const int*)d_in[15];
    const int*   dst  = (const int*)d_in[16];

    float *m1, *q1, *p1, *m2, *q2, *p2;
    cudaGetSymbolAddress((void**)&m1, g_m1);
    cudaGetSymbolAddress((void**)&q1, g_q1);
    cudaGetSymbolAddress((void**)&p1, g_p1);
    cudaGetSymbolAddress((void**)&m2, g_m2);
    cudaGetSymbolAddress((void**)&q2, g_q2);
    cudaGetSymbolAddress((void**)&p2, g_p2);

    __nv_bfloat16 *w0h, *w0l, *wq1h, *wq1l, *wp1h, *wp1l, *wq2h, *wq2l, *wp2h, *wp2l;
    cudaGetSymbolAddress((void**)&w0h, g_w0h);
    cudaGetSymbolAddress((void**)&w0l, g_w0l);
    cudaGetSymbolAddress((void**)&wq1h, g_wq1h);
    cudaGetSymbolAddress((void**)&wq1l, g_wq1l);
    cudaGetSymbolAddress((void**)&wp1h, g_wp1h);
    cudaGetSymbolAddress((void**)&wp1l, g_wp1l);
    cudaGetSymbolAddress((void**)&wq2h, g_wq2h);
    cudaGetSymbolAddress((void**)&wq2l, g_wq2l);
    cudaGetSymbolAddress((void**)&wp2h, g_wp2h);
    cudaGetSymbolAddress((void**)&wp2l, g_wp2l);

    const int gemm_grid = (N_NODES + 127) / 128;  // 391
    const int gat_grid  = (N_NODES + 7) / 8;      // 6250

    // weight prep
    k_prep<<<64, 256>>>(W0, 128 * 128, w0h, w0l);
    k_prep<<<64, 256>>>(Wq1, 128 * 128, wq1h, wq1l);
    k_prep<<<64, 256>>>(Wp1, 128 * 128, wp1h, wp1l);
    k_prep<<<32, 256>>>(Wq2, 128 * 64, wq2h, wq2l);
    k_prep<<<32, 256>>>(Wp2, 128 * 64, wp2h, wp2l);

    // CSR build
    k_zero<<<(N_NODES + 255) / 256, 256>>>();
    k_hist<<<(N_EDGES + 255) / 256, 256>>>(dst);
    k_scan<<<1, 1024>>>();
    k_scatter<<<(N_EDGES + 255) / 256, 256>>>(src, dst);

    // layer 1
    k_gemm_mma<128, true ><<<gemm_grid, 256>>>(x,  w0h,  w0l,  b0,  m1, N_NODES);
    k_gemm_mma<128, false><<<gemm_grid, 256>>>(m1, wq1h, wq1l, bq1, q1, N_NODES);
    k_gemm_mma<128, false><<<gemm_grid, 256>>>(m1, wp1h, wp1l, bp1, p1, N_NODES);
    k_gat128<<<gat_grid, 256>>>(q1, p1, a1, bg2, m2);  // fuses +bg2 and gelu

    // layer 2
    k_gemm_mma<64, false><<<gemm_grid, 256>>>(m2, wq2h, wq2l, bq2, q2, N_NODES);
    k_gemm_mma<64, false><<<gemm_grid, 256>>>(m2, wp2h, wp2l, bp2, p2, N_NODES);
    k_gat64<<<gat_grid, 256>>>(q2, p2, a2, b_out, (float*)d_out);  // fuses +b_out
}

// round 4
// speedup vs baseline: 1.4469x; 1.0304x over previous
#include <cuda_runtime.h>
#include <cuda_bf16.h>
#include <math.h>
#include <stdint.h>

#define N_NODES 50000
#define N_EDGES 800000
#define DH 128
#define DOUT 64
#define XN (N_NODES * DH)

// ---------------- scratch (device globals) ----------------
__device__ __nv_bfloat16 g_xh[XN], g_xl[XN];     // split of x
__device__ __nv_bfloat16 g_m1h[XN], g_m1l[XN];   // split of m1 (gemm1 epilogue)
__device__ __nv_bfloat16 g_m2h[XN], g_m2l[XN];   // split of m2 (gat128 epilogue)
__device__ float g_q1[N_NODES * DH];
__device__ float g_p1[N_NODES * DH];
__device__ float g_q2[N_NODES * DOUT];
__device__ float g_p2[N_NODES * DOUT];
__device__ int   g_cnt[N_NODES];
__device__ int   g_fill[N_NODES];
__device__ int   g_rowptr[N_NODES + 1];
__device__ int   g_csrc[N_EDGES];

// bf16 hi/lo split weights, row-major [K][NO]
__device__ __nv_bfloat16 g_w0h[128 * 128], g_w0l[128 * 128];
__device__ __nv_bfloat16 g_wq1h[128 * 128], g_wq1l[128 * 128];
__device__ __nv_bfloat16 g_wp1h[128 * 128], g_wp1l[128 * 128];
__device__ __nv_bfloat16 g_wq2h[128 * 64], g_wq2l[128 * 64];
__device__ __nv_bfloat16 g_wp2h[128 * 64], g_wp2l[128 * 64];

// ---------------- helpers ----------------
__device__ __forceinline__ float gelu_erf(float x) {
    return 0.5f * x * (1.0f + erff(x * 0.70710678118654752440f));
}

__device__ __forceinline__ uint32_t smem_u32(const void* p) {
    uint32_t a;
    asm("{ .reg .u64 t; cvta.to.shared.u64 t, %1; cvt.u32.u64 %0, t; }" : "=r"(a) : "l"(p));
    return a;
}

__device__ __forceinline__ void ldx4(uint32_t* r, uint32_t addr) {
    asm volatile("ldmatrix.sync.aligned.m8n8.x4.shared.b16 {%0,%1,%2,%3}, [%4];"
                 : "=r"(r[0]), "=r"(r[1]), "=r"(r[2]), "=r"(r[3]) : "r"(addr));
}

__device__ __forceinline__ void ldx4t(uint32_t* r, uint32_t addr) {
    asm volatile("ldmatrix.sync.aligned.m8n8.x4.trans.shared.b16 {%0,%1,%2,%3}, [%4];"
                 : "=r"(r[0]), "=r"(r[1]), "=r"(r[2]), "=r"(r[3]) : "r"(addr));
}

__device__ __forceinline__ void mma16816(float* c, const uint32_t* a, uint32_t b0, uint32_t b1) {
    asm volatile(
        "mma.sync.aligned.m16n8k16.row.col.f32.bf16.bf16.f32 "
        "{%0,%1,%2,%3}, {%4,%5,%6,%7}, {%8,%9}, {%0,%1,%2,%3};"
        : "+f"(c[0]), "+f"(c[1]), "+f"(c[2]), "+f"(c[3])
        : "r"(a[0]), "r"(a[1]), "r"(a[2]), "r"(a[3]), "r"(b0), "r"(b1));
}

__device__ __forceinline__ void split2(float a, float b, uint32_t& hi, uint32_t& lo) {
    __nv_bfloat16 ha = __float2bfloat16(a), hb = __float2bfloat16(b);
    __nv_bfloat16 la = __float2bfloat16(a - __bfloat162float(ha));
    __nv_bfloat16 lb = __float2bfloat16(b - __bfloat162float(hb));
    hi = (uint32_t)__bfloat16_as_ushort(ha) | ((uint32_t)__bfloat16_as_ushort(hb) << 16);
    lo = (uint32_t)__bfloat16_as_ushort(la) | ((uint32_t)__bfloat16_as_ushort(lb) << 16);
}

// ---------------- merged prep: split x and all 5 weights ----------------
__global__ void k_prep_all(const float* __restrict__ x,
                           const float* __restrict__ W0, const float* __restrict__ Wq1,
                           const float* __restrict__ Wp1, const float* __restrict__ Wq2,
                           const float* __restrict__ Wp2) {
    int idx = blockIdx.x * blockDim.x + threadIdx.x;
    const float* srcp;
    __nv_bfloat16 *dh, *dl;
    int off;
    if (idx < XN) {
        srcp = x; dh = g_xh; dl = g_xl; off = idx;
    } else {
        int j = idx - XN;
        if (j < 16384)       { srcp = W0;  dh = g_w0h;  dl = g_w0l;  off = j; }
        else if (j < 32768)  { srcp = Wq1; dh = g_wq1h; dl = g_wq1l; off = j - 16384; }
        else if (j < 49152)  { srcp = Wp1; dh = g_wp1h; dl = g_wp1l; off = j - 32768; }
        else if (j < 57344)  { srcp = Wq2; dh = g_wq2h; dl = g_wq2l; off = j - 49152; }
        else if (j < 65536)  { srcp = Wp2; dh = g_wp2h; dl = g_wp2l; off = j - 57344; }
        else return;
    }
    float v = srcp[off];
    __nv_bfloat16 h = __float2bfloat16(v);
    dh[off] = h;
    dl[off] = __float2bfloat16(v - __bfloat162float(h));
}

// ---------------- CSR build ----------------
__global__ void k_hist(const int* __restrict__ dst) {
    int e = blockIdx.x * blockDim.x + threadIdx.x;
    if (e < N_EDGES) atomicAdd(&g_cnt[dst[e]], 1);
}

__global__ void k_scan() {
    const int NT = 1024;
    const int C = (N_NODES + NT - 1) / NT;
    int t = threadIdx.x;
    int beg = t * C;
    int end = min(N_NODES, beg + C);
    int s = 0;
    for (int i = beg; i < end; i++) s += g_cnt[i];
    __shared__ int sums[NT];
    sums[t] = s;
    __syncthreads();
    for (int off = 1; off < NT; off <<= 1) {
        int v = (t >= off) ? sums[t - off] : 0;
        __syncthreads();
        sums[t] += v;
        __syncthreads();
    }
    int run = (t == 0) ? 0 : sums[t - 1];
    for (int i = beg; i < end; i++) {
        g_rowptr[i] = run;
        g_fill[i] = run;
        run += g_cnt[i];
    }
    if (t == 0) g_rowptr[N_NODES] = N_EDGES;
}

__global__ void k_scatter(const int* __restrict__ src, const int* __restrict__ dst) {
    int e = blockIdx.x * blockDim.x + threadIdx.x;
    if (e < N_EDGES) {
        int pos = atomicAdd(&g_fill[dst[e]], 1);
        g_csrc[pos] = src[e];
    }
}

// ---------------- mma.sync GEMM: C = act(A[M,128] @ W[128,NO] + bias) ----------------
// A pre-split bf16 hi/lo. 256 threads = 8 warps (4m x 2n); K chunked by 32.
// blockIdx.y selects weight/out set (for fused q/p launches).
template <int NO, bool ACT, bool SPLITOUT>
__global__ __launch_bounds__(256, 2) void k_gemm(
    const __nv_bfloat16* __restrict__ Ah, const __nv_bfloat16* __restrict__ Al,
    const __nv_bfloat16* __restrict__ Wh0, const __nv_bfloat16* __restrict__ Wl0,
    const float* __restrict__ bias0, float* __restrict__ Cf0,
    __nv_bfloat16* __restrict__ Ch0, __nv_bfloat16* __restrict__ Cl0,
    const __nv_bfloat16* __restrict__ Wh1, const __nv_bfloat16* __restrict__ Wl1,
    const float* __restrict__ bias1, float* __restrict__ Cf1, int M) {
    constexpr int AP = 40;        // A smem row length in bf16 (32 + 8 pad)
    constexpr int WPAD = NO + 8;
    constexpr int NB = NO / 16;

    const __nv_bfloat16* Wh = blockIdx.y ? Wh1 : Wh0;
    const __nv_bfloat16* Wl = blockIdx.y ? Wl1 : Wl0;
    const float* bias = blockIdx.y ? bias1 : bias0;
    float* Cf = blockIdx.y ? Cf1 : Cf0;

    __shared__ alignas(16) __nv_bfloat16 sAh[128 * AP];
    __shared__ alignas(16) __nv_bfloat16 sAl[128 * AP];
    __shared__ alignas(16) __nv_bfloat16 sWh[32 * WPAD];
    __shared__ alignas(16) __nv_bfloat16 sWl[32 * WPAD];

    const int tid = threadIdx.x;
    const int wid = tid >> 5, lane = tid & 31;
    const int wm = wid & 3, wn = wid >> 2;
    const int row0 = blockIdx.x * 128;

    float acc[2][NB][4];
#pragma unroll
    for (int mb = 0; mb < 2; mb++)
#pragma unroll
        for (int nb = 0; nb < NB; nb++)
#pragma unroll
            for (int j = 0; j < 4; j++) acc[mb][nb][j] = 0.f;

    const uint32_t aBaseH = smem_u32(sAh), aBaseL = smem_u32(sAl);
    const uint32_t wBaseH = smem_u32(sWh), wBaseL = smem_u32(sWl);

    const int a_row = wm * 32 + (lane & 15);
    const int a_col = (lane >> 4) * 8;
    const int b_blk = lane >> 3;
    const int b_rowoff = (b_blk & 1) * 8 + (lane & 7);
    const int b_coladd = wn * (NO / 2) + (b_blk >> 1) * 8;

    const uint4 z4 = make_uint4(0, 0, 0, 0);

    for (int c = 0; c < 4; c++) {
        const int k0 = c * 32;
        // A chunk: 128 rows x 32 bf16 per split -> pure copy
        for (int i = tid; i < 512; i += 256) {
            int r = i >> 2, qq = i & 3;
            int grow = row0 + r;
            uint4 vh = z4, vl = z4;
            if (grow < M) {
                vh = *(const uint4*)(Ah + (size_t)grow * 128 + k0 + qq * 8);
                vl = *(const uint4*)(Al + (size_t)grow * 128 + k0 + qq * 8);
            }
            *(uint4*)(sAh + r * AP + qq * 8) = vh;
            *(uint4*)(sAl + r * AP + qq * 8) = vl;
        }
        // W chunk: 32 k-rows x NO
        for (int i = tid; i < 32 * NO / 8; i += 256) {
            int r = i / (NO / 8), off = (i % (NO / 8)) * 8;
            *(uint4*)(sWh + r * WPAD + off) = *(const uint4*)(Wh + (size_t)(k0 + r) * NO + off);
            *(uint4*)(sWl + r * WPAD + off) = *(const uint4*)(Wl + (size_t)(k0 + r) * NO + off);
        }
        __syncthreads();

#pragma unroll
        for (int kc = 0; kc < 32; kc += 16) {
            uint32_t ah[2][4], al[2][4];
#pragma unroll
            for (int mb = 0; mb < 2; mb++) {
                uint32_t off = (uint32_t)((a_row + mb * 16) * AP + kc + a_col) * 2;
                ldx4(ah[mb], aBaseH + off);
                ldx4(al[mb], aBaseL + off);
            }
#pragma unroll
            for (int nb = 0; nb < NB; nb += 2) {
                uint32_t bh[4], bl[4];
                uint32_t off = (uint32_t)((kc + b_rowoff) * WPAD + nb * 8 + b_coladd) * 2;
                ldx4t(bh, wBaseH + off);
                ldx4t(bl, wBaseL + off);
#pragma unroll
                for (int mb = 0; mb < 2; mb++) {
                    mma16816(acc[mb][nb], ah[mb], bh[0], bh[1]);
                    mma16816(acc[mb][nb + 1], ah[mb], bh[2], bh[3]);
                    mma16816(acc[mb][nb], ah[mb], bl[0], bl[1]);
                    mma16816(acc[mb][nb + 1], ah[mb], bl[2], bl[3]);
                    mma16816(acc[mb][nb], al[mb], bh[0], bh[1]);
                    mma16816(acc[mb][nb + 1], al[mb], bh[2], bh[3]);
                }
            }
        }
        __syncthreads();
    }

    // epilogue
#pragma unroll
    for (int mb = 0; mb < 2; mb++) {
#pragma unroll
        for (int nb = 0; nb < NB; nb++) {
            int col = wn * (NO / 2) + nb * 8 + (lane & 3) * 2;
            float b0 = bias[col], b1 = bias[col + 1];
#pragma unroll
            for (int half = 0; half < 2; half++) {
                int r = row0 + wm * 32 + mb * 16 + (lane >> 2) + half * 8;
                if (r < M) {
                    float o0 = acc[mb][nb][half * 2 + 0] + b0;
                    float o1 = acc[mb][nb][half * 2 + 1] + b1;
                    if (ACT) { o0 = gelu_erf(o0); o1 = gelu_erf(o1); }
                    if (SPLITOUT) {
                        uint32_t hi, lo;
                        split2(o0, o1, hi, lo);
                        *(uint32_t*)(Ch0 + (size_t)r * NO + col) = hi;
                        *(uint32_t*)(Cl0 + (size_t)r * NO + col) = lo;
                    } else {
                        *(float2*)(Cf + (size_t)r * NO + col) = make_float2(o0, o1);
                    }
                }
            }
        }
    }
}

// ---------------- GAT D=128: half-warp per edge stream, 2 edges/warp-iter -------
// out (m2) emitted as bf16 hi/lo split, with +badd and gelu fused.
__global__ __launch_bounds__(256) void k_gat128(const float* __restrict__ q,
                                                const float* __restrict__ p,
                                                const float* __restrict__ avec,
                                                const float* __restrict__ badd,
                                                __nv_bfloat16* __restrict__ outh,
                                                __nv_bfloat16* __restrict__ outl) {
    int w = (blockIdx.x * blockDim.x + threadIdx.x) >> 5;
    int lane = threadIdx.x & 31;
    if (w >= N_NODES) return;
    int half = lane >> 4, hl = lane & 15;

    const float4* q4 = (const float4*)q;
    const float4* p4 = (const float4*)p;
    const float4* a4 = (const float4*)avec;
    float4 qv0 = q4[(size_t)w * 32 + hl * 2];
    float4 qv1 = q4[(size_t)w * 32 + hl * 2 + 1];
    float4 av0 = a4[hl * 2], av1 = a4[hl * 2 + 1];

    int beg = g_rowptr[w];
    int count = g_rowptr[w + 1] - beg;
    int n0 = (count + 1) >> 1;
    int base = beg + half * n0;
    int cnt_h = half ? (count - n0) : n0;

    float denom = 0.f;
    float s0 = 0.f, s1 = 0.f, s2 = 0.f, s3 = 0.f;
    float s4 = 0.f, s5 = 0.f, s6 = 0.f, s7 = 0.f;

    for (int it = 0; it < n0; ++it) {
        bool act = it < cnt_h;
        int s = act ? g_csrc[base + it] : 0;
        float4 pv0 = p4[(size_t)s * 32 + hl * 2];
        float4 pv1 = p4[(size_t)s * 32 + hl * 2 + 1];
        float d0 = qv0.x + pv0.x; d0 = (d0 > 0.f) ? d0 : 0.2f * d0;
        float d1 = qv0.y + pv0.y; d1 = (d1 > 0.f) ? d1 : 0.2f * d1;
        float d2 = qv0.z + pv0.z; d2 = (d2 > 0.f) ? d2 : 0.2f * d2;
        float d3 = qv0.w + pv0.w; d3 = (d3 > 0.f) ? d3 : 0.2f * d3;
        float d4 = qv1.x + pv1.x; d4 = (d4 > 0.f) ? d4 : 0.2f * d4;
        float d5 = qv1.y + pv1.y; d5 = (d5 > 0.f) ? d5 : 0.2f * d5;
        float d6 = qv1.z + pv1.z; d6 = (d6 > 0.f) ? d6 : 0.2f * d6;
        float d7 = qv1.w + pv1.w; d7 = (d7 > 0.f) ? d7 : 0.2f * d7;
        float partial = d0 * av0.x + d1 * av0.y + d2 * av0.z + d3 * av0.w +
                        d4 * av1.x + d5 * av1.y + d6 * av1.z + d7 * av1.w;
#pragma unroll
        for (int o = 8; o; o >>= 1) partial += __shfl_xor_sync(0xffffffffu, partial, o);
        float es = act ? __expf(partial) : 0.f;
        denom += es;
        s0 = fmaf(es, pv0.x, s0); s1 = fmaf(es, pv0.y, s1);
        s2 = fmaf(es, pv0.z, s2); s3 = fmaf(es, pv0.w, s3);
        s4 = fmaf(es, pv1.x, s4); s5 = fmaf(es, pv1.y, s5);
        s6 = fmaf(es, pv1.z, s6); s7 = fmaf(es, pv1.w, s7);
    }
    // merge halves
    denom += __shfl_xor_sync(0xffffffffu, denom, 16);
    s0 += __shfl_xor_sync(0xffffffffu, s0, 16);
    s1 += __shfl_xor_sync(0xffffffffu, s1, 16);
    s2 += __shfl_xor_sync(0xffffffffu, s2, 16);
    s3 += __shfl_xor_sync(0xffffffffu, s3, 16);
    s4 += __shfl_xor_sync(0xffffffffu, s4, 16);
    s5 += __shfl_xor_sync(0xffffffffu, s5, 16);
    s6 += __shfl_xor_sync(0xffffffffu, s6, 16);
    s7 += __shfl_xor_sync(0xffffffffu, s7, 16);

    if (half == 0) {
        float inv = (count > 0) ? 1.f / denom : 0.f;
        int col = hl * 8;
        float v0 = gelu_erf(fmaf(s0, inv, badd[col + 0]));
        float v1 = gelu_erf(fmaf(s1, inv, badd[col + 1]));
        float v2 = gelu_erf(fmaf(s2, inv, badd[col + 2]));
        float v3 = gelu_erf(fmaf(s3, inv, badd[col + 3]));
        float v4 = gelu_erf(fmaf(s4, inv, badd[col + 4]));
        float v5 = gelu_erf(fmaf(s5, inv, badd[col + 5]));
        float v6 = gelu_erf(fmaf(s6, inv, badd[col + 6]));
        float v7 = gelu_erf(fmaf(s7, inv, badd[col + 7]));
        uint32_t h01, l01, h23, l23, h45, l45, h67, l67;
        split2(v0, v1, h01, l01);
        split2(v2, v3, h23, l23);
        split2(v4, v5, h45, l45);
        split2(v6, v7, h67, l67);
        *(uint4*)(outh + (size_t)w * 128 + col) = make_uint4(h01, h23, h45, h67);
        *(uint4*)(outl + (size_t)w * 128 + col) = make_uint4(l01, l23, l45, l67);
    }
}

// ---------------- GAT D=64: half-warp per edge stream; out = agg + b_out --------
__global__ __launch_bounds__(256) void k_gat64(const float* __restrict__ q,
                                               const float* __restrict__ p,
                                               const float* __restrict__ avec,
                                               const float* __restrict__ bout,
                                               float* __restrict__ out) {
    int w = (blockIdx.x * blockDim.x + threadIdx.x) >> 5;
    int lane = threadIdx.x & 31;
    if (w >= N_NODES) return;
    int half = lane >> 4, hl = lane & 15;

    const float4* q4 = (const float4*)q;
    const float4* p4 = (const float4*)p;
    float4 qv = q4[(size_t)w * 16 + hl];
    float4 av = ((const float4*)avec)[hl];

    int beg = g_rowptr[w];
    int count = g_rowptr[w + 1] - beg;
    int n0 = (count + 1) >> 1;
    int base = beg + half * n0;
    int cnt_h = half ? (count - n0) : n0;

    float denom = 0.f;
    float s0 = 0.f, s1 = 0.f, s2 = 0.f, s3 = 0.f;

    for (int it = 0; it < n0; ++it) {
        bool act = it < cnt_h;
        int s = act ? g_csrc[base + it] : 0;
        float4 pv = p4[(size_t)s * 16 + hl];
        float d0 = qv.x + pv.x; d0 = (d0 > 0.f) ? d0 : 0.2f * d0;
        float d1 = qv.y + pv.y; d1 = (d1 > 0.f) ? d1 : 0.2f * d1;
        float d2 = qv.z + pv.z; d2 = (d2 > 0.f) ? d2 : 0.2f * d2;
        float d3 = qv.w + pv.w; d3 = (d3 > 0.f) ? d3 : 0.2f * d3;
        float partial = d0 * av.x + d1 * av.y + d2 * av.z + d3 * av.w;
#pragma unroll
        for (int o = 8; o; o >>= 1) partial += __shfl_xor_sync(0xffffffffu, partial, o);
        float es = act ? __expf(partial) : 0.f;
        denom += es;
        s0 = fmaf(es, pv.x, s0); s1 = fmaf(es, pv.y, s1);
        s2 = fmaf(es, pv.z, s2); s3 = fmaf(es, pv.w, s3);
    }
    denom += __shfl_xor_sync(0xffffffffu, denom, 16);
    s0 += __shfl_xor_sync(0xffffffffu, s0, 16);
    s1 += __shfl_xor_sync(0xffffffffu, s1, 16);
    s2 += __shfl_xor_sync(0xffffffffu, s2, 16);
    s3 += __shfl_xor_sync(0xffffffffu, s3, 16);

    if (half == 0) {
        float inv = (count > 0) ? 1.f / denom : 0.f;
        int col = hl * 4;
        float4 o;
        o.x = fmaf(s0, inv, bout[col + 0]);
        o.y = fmaf(s1, inv, bout[col + 1]);
        o.z = fmaf(s2, inv, bout[col + 2]);
        o.w = fmaf(s3, inv, bout[col + 3]);
        ((float4*)out)[(size_t)w * 16 + hl] = o;
    }
}

// ---------------- launch ----------------
extern "C" void kernel_launch(void* const* d_in, const int* in_sizes, int n_in,
                              void* d_out, int out_size) {
    const float* x    = (const float*)d_in[0];
    const float* W0   = (const float*)d_in[1];
    const float* b0   = (const float*)d_in[2];
    const float* Wq1  = (const float*)d_in[3];
    const float* bq1  = (const float*)d_in[4];
    const float* Wp1  = (const float*)d_in[5];
    const float* bp1  = (const float*)d_in[6];
    const float* a1   = (const float*)d_in[7];
    const float* bg2  = (const float*)d_in[8];
    const float* Wq2  = (const float*)d_in[9];
    const float* bq2  = (const float*)d_in[10];
    const float* Wp2  = (const float*)d_in[11];
    const float* bp2  = (const float*)d_in[12];
    const float* a2   = (const float*)d_in[13];
    const float* b_out= (const float*)d_in[14];
    const int*   src  = (const int*)d_in[15];
    const int*   dst  = (const int*)d_in[16];

    float *q1, *p1, *q2, *p2;
    cudaGetSymbolAddress((void**)&q1, g_q1);
    cudaGetSymbolAddress((void**)&p1, g_p1);
    cudaGetSymbolAddress((void**)&q2, g_q2);
    cudaGetSymbolAddress((void**)&p2, g_p2);

    __nv_bfloat16 *xh, *xl, *m1h, *m1l, *m2h, *m2l;
    cudaGetSymbolAddress((void**)&xh, g_xh);
    cudaGetSymbolAddress((void**)&xl, g_xl);
    cudaGetSymbolAddress((void**)&m1h, g_m1h);
    cudaGetSymbolAddress((void**)&m1l, g_m1l);
    cudaGetSymbolAddress((void**)&m2h, g_m2h);
    cudaGetSymbolAddress((void**)&m2l, g_m2l);

    __nv_bfloat16 *w0h, *w0l, *wq1h, *wq1l, *wp1h, *wp1l, *wq2h, *wq2l, *wp2h, *wp2l;
    cudaGetSymbolAddress((void**)&w0h, g_w0h);
    cudaGetSymbolAddress((void**)&w0l, g_w0l);
    cudaGetSymbolAddress((void**)&wq1h, g_wq1h);
    cudaGetSymbolAddress((void**)&wq1l, g_wq1l);
    cudaGetSymbolAddress((void**)&wp1h, g_wp1h);
    cudaGetSymbolAddress((void**)&wp1l, g_wp1l);
    cudaGetSymbolAddress((void**)&wq2h, g_wq2h);
    cudaGetSymbolAddress((void**)&wq2l, g_wq2l);
    cudaGetSymbolAddress((void**)&wp2h, g_wp2h);
    cudaGetSymbolAddress((void**)&wp2l, g_wp2l);

    int* cntp;
    cudaGetSymbolAddress((void**)&cntp, g_cnt);

    const int gemm_gx = (N_NODES + 127) / 128;  // 391
    const dim3 qp_grid(gemm_gx, 2);
    const int gat_grid = (N_NODES + 7) / 8;     // 6250

    // prep: split x + all weights (one launch)
    k_prep_all<<<(XN + 65536 + 255) / 256, 256>>>(x, W0, Wq1, Wp1, Wq2, Wp2);

    // CSR build
    cudaMemsetAsync(cntp, 0, N_NODES * sizeof(int));
    k_hist<<<(N_EDGES + 255) / 256, 256>>>(dst);
    k_scan<<<1, 1024>>>();
    k_scatter<<<(N_EDGES + 255) / 256, 256>>>(src, dst);

    // layer 1: m1(split) = gelu(x@W0+b0); q1,p1 in one fused launch
    k_gemm<128, true, true><<<gemm_gx, 256>>>(xh, xl, w0h, w0l, b0, nullptr, m1h, m1l,
                                              w0h, w0l, b0, nullptr, N_NODES);
    k_gemm<128, false, false><<<qp_grid, 256>>>(m1h, m1l, wq1h, wq1l, bq1, q1, nullptr, nullptr,
                                                wp1h, wp1l, bp1, p1, N_NODES);
    k_gat128<<<gat_grid, 256>>>(q1, p1, a1, bg2, m2h, m2l);

    // layer 2: q2,p2 fused; gat64 writes final output
    k_gemm<64, false, false><<<qp_grid, 256>>>(m2h, m2l, wq2h, wq2l, bq2, q2, nullptr, nullptr,
                                               wp2h, wp2l, bp2, p2, N_NODES);
    k_gat64<<<gat_grid, 256>>>(q2, p2, a2, b_out, (float*)d_out);
}

// round 5
// speedup vs baseline: 1.9090x; 1.3193x over previous
#include <cuda_runtime.h>
#include <cuda_bf16.h>
#include <math.h>
#include <stdint.h>

#define N_NODES 50000
#define N_EDGES 800000
#define DH 128
#define DOUT 64
#define XN (N_NODES * DH)
#define SCAN_BLOCKS 196   // 196*256 = 50176 >= N_NODES

// ---------------- scratch (device globals) ----------------
__device__ __nv_bfloat16 g_xh[XN], g_xl[XN];
__device__ __nv_bfloat16 g_m1h[XN], g_m1l[XN];
__device__ __nv_bfloat16 g_m2h[XN], g_m2l[XN];
__device__ float g_q1[N_NODES * DH];
__device__ float g_p1[N_NODES * DH];
__device__ float g_q2[N_NODES * DOUT];
__device__ float g_p2[N_NODES * DOUT];
__device__ int   g_cnt[N_NODES];
__device__ int   g_fill[N_NODES];
__device__ int   g_rowptr[N_NODES + 1];
__device__ int   g_csrc[N_EDGES];
__device__ int   g_part[SCAN_BLOCKS];
__device__ int   g_partoff[SCAN_BLOCKS];

__device__ __nv_bfloat16 g_w0h[128 * 128], g_w0l[128 * 128];
__device__ __nv_bfloat16 g_wq1h[128 * 128], g_wq1l[128 * 128];
__device__ __nv_bfloat16 g_wp1h[128 * 128], g_wp1l[128 * 128];
__device__ __nv_bfloat16 g_wq2h[128 * 64], g_wq2l[128 * 64];
__device__ __nv_bfloat16 g_wp2h[128 * 64], g_wp2l[128 * 64];

// ---------------- helpers ----------------
__device__ __forceinline__ float gelu_erf(float x) {
    return 0.5f * x * (1.0f + erff(x * 0.70710678118654752440f));
}

__device__ __forceinline__ uint32_t smem_u32(const void* p) {
    uint32_t a;
    asm("{ .reg .u64 t; cvta.to.shared.u64 t, %1; cvt.u32.u64 %0, t; }" : "=r"(a) : "l"(p));
    return a;
}

__device__ __forceinline__ void ldx4(uint32_t* r, uint32_t addr) {
    asm volatile("ldmatrix.sync.aligned.m8n8.x4.shared.b16 {%0,%1,%2,%3}, [%4];"
                 : "=r"(r[0]), "=r"(r[1]), "=r"(r[2]), "=r"(r[3]) : "r"(addr));
}

__device__ __forceinline__ void ldx4t(uint32_t* r, uint32_t addr) {
    asm volatile("ldmatrix.sync.aligned.m8n8.x4.trans.shared.b16 {%0,%1,%2,%3}, [%4];"
                 : "=r"(r[0]), "=r"(r[1]), "=r"(r[2]), "=r"(r[3]) : "r"(addr));
}

__device__ __forceinline__ void mma16816(float* c, const uint32_t* a, uint32_t b0, uint32_t b1) {
    asm volatile(
        "mma.sync.aligned.m16n8k16.row.col.f32.bf16.bf16.f32 "
        "{%0,%1,%2,%3}, {%4,%5,%6,%7}, {%8,%9}, {%0,%1,%2,%3};"
        : "+f"(c[0]), "+f"(c[1]), "+f"(c[2]), "+f"(c[3])
        : "r"(a[0]), "r"(a[1]), "r"(a[2]), "r"(a[3]), "r"(b0), "r"(b1));
}

__device__ __forceinline__ void split2(float a, float b, uint32_t& hi, uint32_t& lo) {
    __nv_bfloat16 ha = __float2bfloat16(a), hb = __float2bfloat16(b);
    __nv_bfloat16 la = __float2bfloat16(a - __bfloat162float(ha));
    __nv_bfloat16 lb = __float2bfloat16(b - __bfloat162float(hb));
    hi = (uint32_t)__bfloat16_as_ushort(ha) | ((uint32_t)__bfloat16_as_ushort(hb) << 16);
    lo = (uint32_t)__bfloat16_as_ushort(la) | ((uint32_t)__bfloat16_as_ushort(lb) << 16);
}

// ---------------- merged prep ----------------
__global__ void k_prep_all(const float* __restrict__ x,
                           const float* __restrict__ W0, const float* __restrict__ Wq1,
                           const float* __restrict__ Wp1, const float* __restrict__ Wq2,
                           const float* __restrict__ Wp2) {
    int idx = blockIdx.x * blockDim.x + threadIdx.x;
    const float* srcp;
    __nv_bfloat16 *dh, *dl;
    int off;
    if (idx < XN) {
        srcp = x; dh = g_xh; dl = g_xl; off = idx;
    } else {
        int j = idx - XN;
        if (j < 16384)       { srcp = W0;  dh = g_w0h;  dl = g_w0l;  off = j; }
        else if (j < 32768)  { srcp = Wq1; dh = g_wq1h; dl = g_wq1l; off = j - 16384; }
        else if (j < 49152)  { srcp = Wp1; dh = g_wp1h; dl = g_wp1l; off = j - 32768; }
        else if (j < 57344)  { srcp = Wq2; dh = g_wq2h; dl = g_wq2l; off = j - 49152; }
        else if (j < 65536)  { srcp = Wp2; dh = g_wp2h; dl = g_wp2l; off = j - 57344; }
        else return;
    }
    float v = srcp[off];
    __nv_bfloat16 h = __float2bfloat16(v);
    dh[off] = h;
    dl[off] = __float2bfloat16(v - __bfloat162float(h));
}

// ---------------- CSR build (vectorized + parallel scan) ----------------
__global__ void k_hist(const int* __restrict__ dst) {
    int t = blockIdx.x * blockDim.x + threadIdx.x;
    if (t < N_EDGES / 4) {
        int4 d = ((const int4*)dst)[t];
        atomicAdd(&g_cnt[d.x], 1);
        atomicAdd(&g_cnt[d.y], 1);
        atomicAdd(&g_cnt[d.z], 1);
        atomicAdd(&g_cnt[d.w], 1);
    }
}

__global__ void k_scan_part() {
    __shared__ int sd[256];
    int i = blockIdx.x * 256 + threadIdx.x;
    int v = (i < N_NODES) ? g_cnt[i] : 0;
    sd[threadIdx.x] = v;
    __syncthreads();
#pragma unroll
    for (int off = 128; off; off >>= 1) {
        if (threadIdx.x < off) sd[threadIdx.x] += sd[threadIdx.x + off];
        __syncthreads();
    }
    if (threadIdx.x == 0) g_part[blockIdx.x] = sd[0];
}

__global__ void k_scan_mid() {
    __shared__ int sd[256];
    int t = threadIdx.x;
    int v = (t < SCAN_BLOCKS) ? g_part[t] : 0;
    sd[t] = v;
    __syncthreads();
#pragma unroll
    for (int off = 1; off < 256; off <<= 1) {
        int u = (t >= off) ? sd[t - off] : 0;
        __syncthreads();
        sd[t] += u;
        __syncthreads();
    }
    if (t < SCAN_BLOCKS) g_partoff[t] = sd[t] - v;  // exclusive
}

__global__ void k_scan_final() {
    __shared__ int sd[256];
    int i = blockIdx.x * 256 + threadIdx.x;
    int t = threadIdx.x;
    int v = (i < N_NODES) ? g_cnt[i] : 0;
    sd[t] = v;
    __syncthreads();
#pragma unroll
    for (int off = 1; off < 256; off <<= 1) {
        int u = (t >= off) ? sd[t - off] : 0;
        __syncthreads();
        sd[t] += u;
        __syncthreads();
    }
    if (i < N_NODES) {
        int excl = g_partoff[blockIdx.x] + sd[t] - v;
        g_rowptr[i] = excl;
        g_fill[i] = excl;
    }
    if (i == N_NODES - 1) g_rowptr[N_NODES] = N_EDGES;
}

__global__ void k_scatter(const int* __restrict__ src, const int* __restrict__ dst) {
    int t = blockIdx.x * blockDim.x + threadIdx.x;
    if (t < N_EDGES / 4) {
        int4 d = ((const int4*)dst)[t];
        int4 s = ((const int4*)src)[t];
        g_csrc[atomicAdd(&g_fill[d.x], 1)] = s.x;
        g_csrc[atomicAdd(&g_fill[d.y], 1)] = s.y;
        g_csrc[atomicAdd(&g_fill[d.z], 1)] = s.z;
        g_csrc[atomicAdd(&g_fill[d.w], 1)] = s.w;
    }
}

// ---------------- mma.sync GEMM (unchanged from R4) ----------------
template <int NO, bool ACT, bool SPLITOUT>
__global__ __launch_bounds__(256, 2) void k_gemm(
    const __nv_bfloat16* __restrict__ Ah, const __nv_bfloat16* __restrict__ Al,
    const __nv_bfloat16* __restrict__ Wh0, const __nv_bfloat16* __restrict__ Wl0,
    const float* __restrict__ bias0, float* __restrict__ Cf0,
    __nv_bfloat16* __restrict__ Ch0, __nv_bfloat16* __restrict__ Cl0,
    const __nv_bfloat16* __restrict__ Wh1, const __nv_bfloat16* __restrict__ Wl1,
    const float* __restrict__ bias1, float* __restrict__ Cf1, int M) {
    constexpr int AP = 40;
    constexpr int WPAD = NO + 8;
    constexpr int NB = NO / 16;

    const __nv_bfloat16* Wh = blockIdx.y ? Wh1 : Wh0;
    const __nv_bfloat16* Wl = blockIdx.y ? Wl1 : Wl0;
    const float* bias = blockIdx.y ? bias1 : bias0;
    float* Cf = blockIdx.y ? Cf1 : Cf0;

    __shared__ alignas(16) __nv_bfloat16 sAh[128 * AP];
    __shared__ alignas(16) __nv_bfloat16 sAl[128 * AP];
    __shared__ alignas(16) __nv_bfloat16 sWh[32 * WPAD];
    __shared__ alignas(16) __nv_bfloat16 sWl[32 * WPAD];

    const int tid = threadIdx.x;
    const int wid = tid >> 5, lane = tid & 31;
    const int wm = wid & 3, wn = wid >> 2;
    const int row0 = blockIdx.x * 128;

    float acc[2][NB][4];
#pragma unroll
    for (int mb = 0; mb < 2; mb++)
#pragma unroll
        for (int nb = 0; nb < NB; nb++)
#pragma unroll
            for (int j = 0; j < 4; j++) acc[mb][nb][j] = 0.f;

    const uint32_t aBaseH = smem_u32(sAh), aBaseL = smem_u32(sAl);
    const uint32_t wBaseH = smem_u32(sWh), wBaseL = smem_u32(sWl);

    const int a_row = wm * 32 + (lane & 15);
    const int a_col = (lane >> 4) * 8;
    const int b_blk = lane >> 3;
    const int b_rowoff = (b_blk & 1) * 8 + (lane & 7);
    const int b_coladd = wn * (NO / 2) + (b_blk >> 1) * 8;

    const uint4 z4 = make_uint4(0, 0, 0, 0);

    for (int c = 0; c < 4; c++) {
        const int k0 = c * 32;
        for (int i = tid; i < 512; i += 256) {
            int r = i >> 2, qq = i & 3;
            int grow = row0 + r;
            uint4 vh = z4, vl = z4;
            if (grow < M) {
                vh = *(const uint4*)(Ah + (size_t)grow * 128 + k0 + qq * 8);
                vl = *(const uint4*)(Al + (size_t)grow * 128 + k0 + qq * 8);
            }
            *(uint4*)(sAh + r * AP + qq * 8) = vh;
            *(uint4*)(sAl + r * AP + qq * 8) = vl;
        }
        for (int i = tid; i < 32 * NO / 8; i += 256) {
            int r = i / (NO / 8), off = (i % (NO / 8)) * 8;
            *(uint4*)(sWh + r * WPAD + off) = *(const uint4*)(Wh + (size_t)(k0 + r) * NO + off);
            *(uint4*)(sWl + r * WPAD + off) = *(const uint4*)(Wl + (size_t)(k0 + r) * NO + off);
        }
        __syncthreads();

#pragma unroll
        for (int kc = 0; kc < 32; kc += 16) {
            uint32_t ah[2][4], al[2][4];
#pragma unroll
            for (int mb = 0; mb < 2; mb++) {
                uint32_t off = (uint32_t)((a_row + mb * 16) * AP + kc + a_col) * 2;
                ldx4(ah[mb], aBaseH + off);
                ldx4(al[mb], aBaseL + off);
            }
#pragma unroll
            for (int nb = 0; nb < NB; nb += 2) {
                uint32_t bh[4], bl[4];
                uint32_t off = (uint32_t)((kc + b_rowoff) * WPAD + nb * 8 + b_coladd) * 2;
                ldx4t(bh, wBaseH + off);
                ldx4t(bl, wBaseL + off);
#pragma unroll
                for (int mb = 0; mb < 2; mb++) {
                    mma16816(acc[mb][nb], ah[mb], bh[0], bh[1]);
                    mma16816(acc[mb][nb + 1], ah[mb], bh[2], bh[3]);
                    mma16816(acc[mb][nb], ah[mb], bl[0], bl[1]);
                    mma16816(acc[mb][nb + 1], ah[mb], bl[2], bl[3]);
                    mma16816(acc[mb][nb], al[mb], bh[0], bh[1]);
                    mma16816(acc[mb][nb + 1], al[mb], bh[2], bh[3]);
                }
            }
        }
        __syncthreads();
    }

#pragma unroll
    for (int mb = 0; mb < 2; mb++) {
#pragma unroll
        for (int nb = 0; nb < NB; nb++) {
            int col = wn * (NO / 2) + nb * 8 + (lane & 3) * 2;
            float b0 = bias[col], b1 = bias[col + 1];
#pragma unroll
            for (int half = 0; half < 2; half++) {
                int r = row0 + wm * 32 + mb * 16 + (lane >> 2) + half * 8;
                if (r < M) {
                    float o0 = acc[mb][nb][half * 2 + 0] + b0;
                    float o1 = acc[mb][nb][half * 2 + 1] + b1;
                    if (ACT) { o0 = gelu_erf(o0); o1 = gelu_erf(o1); }
                    if (SPLITOUT) {
                        uint32_t hi, lo;
                        split2(o0, o1, hi, lo);
                        *(uint32_t*)(Ch0 + (size_t)r * NO + col) = hi;
                        *(uint32_t*)(Cl0 + (size_t)r * NO + col) = lo;
                    } else {
                        *(float2*)(Cf + (size_t)r * NO + col) = make_float2(o0, o1);
                    }
                }
            }
        }
    }
}

// ---------------- GAT D=128: half-warp edge streams, 2-edge ILP unroll ----------
__global__ __launch_bounds__(256) void k_gat128(const float* __restrict__ q,
                                                const float* __restrict__ p,
                                                const float* __restrict__ avec,
                                                const float* __restrict__ badd,
                                                __nv_bfloat16* __restrict__ outh,
                                                __nv_bfloat16* __restrict__ outl) {
    int w = (blockIdx.x * blockDim.x + threadIdx.x) >> 5;
    int lane = threadIdx.x & 31;
    if (w >= N_NODES) return;
    int half = lane >> 4, hl = lane & 15;

    const float4* q4 = (const float4*)q;
    const float4* p4 = (const float4*)p;
    const float4* a4 = (const float4*)avec;
    float4 qv0 = q4[(size_t)w * 32 + hl * 2];
    float4 qv1 = q4[(size_t)w * 32 + hl * 2 + 1];
    float4 av0 = a4[hl * 2], av1 = a4[hl * 2 + 1];

    int beg = g_rowptr[w];
    int count = g_rowptr[w + 1] - beg;
    int n0 = (count + 1) >> 1;
    int base = beg + half * n0;
    int cnt_h = half ? (count - n0) : n0;

    float denom = 0.f;
    float s0 = 0.f, s1 = 0.f, s2 = 0.f, s3 = 0.f;
    float s4 = 0.f, s5 = 0.f, s6 = 0.f, s7 = 0.f;

    for (int it = 0; it < n0; it += 2) {
        bool actA = it < cnt_h;
        bool actB = (it + 1) < cnt_h;
        int sA = actA ? g_csrc[base + it] : 0;
        int sB = actB ? g_csrc[base + it + 1] : 0;
        float4 pA0 = p4[(size_t)sA * 32 + hl * 2];
        float4 pA1 = p4[(size_t)sA * 32 + hl * 2 + 1];
        float4 pB0 = p4[(size_t)sB * 32 + hl * 2];
        float4 pB1 = p4[(size_t)sB * 32 + hl * 2 + 1];

        float dA0 = qv0.x + pA0.x; dA0 = (dA0 > 0.f) ? dA0 : 0.2f * dA0;
        float dA1 = qv0.y + pA0.y; dA1 = (dA1 > 0.f) ? dA1 : 0.2f * dA1;
        float dA2 = qv0.z + pA0.z; dA2 = (dA2 > 0.f) ? dA2 : 0.2f * dA2;
        float dA3 = qv0.w + pA0.w; dA3 = (dA3 > 0.f) ? dA3 : 0.2f * dA3;
        float dA4 = qv1.x + pA1.x; dA4 = (dA4 > 0.f) ? dA4 : 0.2f * dA4;
        float dA5 = qv1.y + pA1.y; dA5 = (dA5 > 0.f) ? dA5 : 0.2f * dA5;
        float dA6 = qv1.z + pA1.z; dA6 = (dA6 > 0.f) ? dA6 : 0.2f * dA6;
        float dA7 = qv1.w + pA1.w; dA7 = (dA7 > 0.f) ? dA7 : 0.2f * dA7;
        float pa = dA0 * av0.x + dA1 * av0.y + dA2 * av0.z + dA3 * av0.w +
                   dA4 * av1.x + dA5 * av1.y + dA6 * av1.z + dA7 * av1.w;

        float dB0 = qv0.x + pB0.x; dB0 = (dB0 > 0.f) ? dB0 : 0.2f * dB0;
        float dB1 = qv0.y + pB0.y; dB1 = (dB1 > 0.f) ? dB1 : 0.2f * dB1;
        float dB2 = qv0.z + pB0.z; dB2 = (dB2 > 0.f) ? dB2 : 0.2f * dB2;
        float dB3 = qv0.w + pB0.w; dB3 = (dB3 > 0.f) ? dB3 : 0.2f * dB3;
        float dB4 = qv1.x + pB1.x; dB4 = (dB4 > 0.f) ? dB4 : 0.2f * dB4;
        float dB5 = qv1.y + pB1.y; dB5 = (dB5 > 0.f) ? dB5 : 0.2f * dB5;
        float dB6 = qv1.z + pB1.z; dB6 = (dB6 > 0.f) ? dB6 : 0.2f * dB6;
        float dB7 = qv1.w + pB1.w; dB7 = (dB7 > 0.f) ? dB7 : 0.2f * dB7;
        float pb = dB0 * av0.x + dB1 * av0.y + dB2 * av0.z + dB3 * av0.w +
                   dB4 * av1.x + dB5 * av1.y + dB6 * av1.z + dB7 * av1.w;

#pragma unroll
        for (int o = 8; o; o >>= 1) {
            pa += __shfl_xor_sync(0xffffffffu, pa, o);
            pb += __shfl_xor_sync(0xffffffffu, pb, o);
        }
        float esA = actA ? __expf(pa) : 0.f;
        float esB = actB ? __expf(pb) : 0.f;
        denom += esA + esB;
        s0 = fmaf(esA, pA0.x, fmaf(esB, pB0.x, s0));
        s1 = fmaf(esA, pA0.y, fmaf(esB, pB0.y, s1));
        s2 = fmaf(esA, pA0.z, fmaf(esB, pB0.z, s2));
        s3 = fmaf(esA, pA0.w, fmaf(esB, pB0.w, s3));
        s4 = fmaf(esA, pA1.x, fmaf(esB, pB1.x, s4));
        s5 = fmaf(esA, pA1.y, fmaf(esB, pB1.y, s5));
        s6 = fmaf(esA, pA1.z, fmaf(esB, pB1.z, s6));
        s7 = fmaf(esA, pA1.w, fmaf(esB, pB1.w, s7));
    }
    denom += __shfl_xor_sync(0xffffffffu, denom, 16);
    s0 += __shfl_xor_sync(0xffffffffu, s0, 16);
    s1 += __shfl_xor_sync(0xffffffffu, s1, 16);
    s2 += __shfl_xor_sync(0xffffffffu, s2, 16);
    s3 += __shfl_xor_sync(0xffffffffu, s3, 16);
    s4 += __shfl_xor_sync(0xffffffffu, s4, 16);
    s5 += __shfl_xor_sync(0xffffffffu, s5, 16);
    s6 += __shfl_xor_sync(0xffffffffu, s6, 16);
    s7 += __shfl_xor_sync(0xffffffffu, s7, 16);

    if (half == 0) {
        float inv = (count > 0) ? 1.f / denom : 0.f;
        int col = hl * 8;
        float v0 = gelu_erf(fmaf(s0, inv, badd[col + 0]));
        float v1 = gelu_erf(fmaf(s1, inv, badd[col + 1]));
        float v2 = gelu_erf(fmaf(s2, inv, badd[col + 2]));
        float v3 = gelu_erf(fmaf(s3, inv, badd[col + 3]));
        float v4 = gelu_erf(fmaf(s4, inv, badd[col + 4]));
        float v5 = gelu_erf(fmaf(s5, inv, badd[col + 5]));
        float v6 = gelu_erf(fmaf(s6, inv, badd[col + 6]));
        float v7 = gelu_erf(fmaf(s7, inv, badd[col + 7]));
        uint32_t h01, l01, h23, l23, h45, l45, h67, l67;
        split2(v0, v1, h01, l01);
        split2(v2, v3, h23, l23);
        split2(v4, v5, h45, l45);
        split2(v6, v7, h67, l67);
        *(uint4*)(outh + (size_t)w * 128 + col) = make_uint4(h01, h23, h45, h67);
        *(uint4*)(outl + (size_t)w * 128 + col) = make_uint4(l01, l23, l45, l67);
    }
}

// ---------------- GAT D=64: half-warp edge streams, 2-edge ILP unroll -----------
__global__ __launch_bounds__(256) void k_gat64(const float* __restrict__ q,
                                               const float* __restrict__ p,
                                               const float* __restrict__ avec,
                                               const float* __restrict__ bout,
                                               float* __restrict__ out) {
    int w = (blockIdx.x * blockDim.x + threadIdx.x) >> 5;
    int lane = threadIdx.x & 31;
    if (w >= N_NODES) return;
    int half = lane >> 4, hl = lane & 15;

    const float4* q4 = (const float4*)q;
    const float4* p4 = (const float4*)p;
    float4 qv = q4[(size_t)w * 16 + hl];
    float4 av = ((const float4*)avec)[hl];

    int beg = g_rowptr[w];
    int count = g_rowptr[w + 1] - beg;
    int n0 = (count + 1) >> 1;
    int base = beg + half * n0;
    int cnt_h = half ? (count - n0) : n0;

    float denom = 0.f;
    float s0 = 0.f, s1 = 0.f, s2 = 0.f, s3 = 0.f;

    for (int it = 0; it < n0; it += 2) {
        bool actA = it < cnt_h;
        bool actB = (it + 1) < cnt_h;
        int sA = actA ? g_csrc[base + it] : 0;
        int sB = actB ? g_csrc[base + it + 1] : 0;
        float4 pA = p4[(size_t)sA * 16 + hl];
        float4 pB = p4[(size_t)sB * 16 + hl];

        float dA0 = qv.x + pA.x; dA0 = (dA0 > 0.f) ? dA0 : 0.2f * dA0;
        float dA1 = qv.y + pA.y; dA1 = (dA1 > 0.f) ? dA1 : 0.2f * dA1;
        float dA2 = qv.z + pA.z; dA2 = (dA2 > 0.f) ? dA2 : 0.2f * dA2;
        float dA3 = qv.w + pA.w; dA3 = (dA3 > 0.f) ? dA3 : 0.2f * dA3;
        float pa = dA0 * av.x + dA1 * av.y + dA2 * av.z + dA3 * av.w;

        float dB0 = qv.x + pB.x; dB0 = (dB0 > 0.f) ? dB0 : 0.2f * dB0;
        float dB1 = qv.y + pB.y; dB1 = (dB1 > 0.f) ? dB1 : 0.2f * dB1;
        float dB2 = qv.z + pB.z; dB2 = (dB2 > 0.f) ? dB2 : 0.2f * dB2;
        float dB3 = qv.w + pB.w; dB3 = (dB3 > 0.f) ? dB3 : 0.2f * dB3;
        float pb = dB0 * av.x + dB1 * av.y + dB2 * av.z + dB3 * av.w;

#pragma unroll
        for (int o = 8; o; o >>= 1) {
            pa += __shfl_xor_sync(0xffffffffu, pa, o);
            pb += __shfl_xor_sync(0xffffffffu, pb, o);
        }
        float esA = actA ? __expf(pa) : 0.f;
        float esB = actB ? __expf(pb) : 0.f;
        denom += esA + esB;
        s0 = fmaf(esA, pA.x, fmaf(esB, pB.x, s0));
        s1 = fmaf(esA, pA.y, fmaf(esB, pB.y, s1));
        s2 = fmaf(esA, pA.z, fmaf(esB, pB.z, s2));
        s3 = fmaf(esA, pA.w, fmaf(esB, pB.w, s3));
    }
    denom += __shfl_xor_sync(0xffffffffu, denom, 16);
    s0 += __shfl_xor_sync(0xffffffffu, s0, 16);
    s1 += __shfl_xor_sync(0xffffffffu, s1, 16);
    s2 += __shfl_xor_sync(0xffffffffu, s2, 16);
    s3 += __shfl_xor_sync(0xffffffffu, s3, 16);

    if (half == 0) {
        float inv = (count > 0) ? 1.f / denom : 0.f;
        int col = hl * 4;
        float4 o;
        o.x = fmaf(s0, inv, bout[col + 0]);
        o.y = fmaf(s1, inv, bout[col + 1]);
        o.z = fmaf(s2, inv, bout[col + 2]);
        o.w = fmaf(s3, inv, bout[col + 3]);
        ((float4*)out)[(size_t)w * 16 + hl] = o;
    }
}

// ---------------- launch ----------------
extern "C" void kernel_launch(void* const* d_in, const int* in_sizes, int n_in,
                              void* d_out, int out_size) {
    const float* x    = (const float*)d_in[0];
    const float* W0   = (const float*)d_in[1];
    const float* b0   = (const float*)d_in[2];
    const float* Wq1  = (const float*)d_in[3];
    const float* bq1  = (const float*)d_in[4];
    const float* Wp1  = (const float*)d_in[5];
    const float* bp1  = (const float*)d_in[6];
    const float* a1   = (const float*)d_in[7];
    const float* bg2  = (const float*)d_in[8];
    const float* Wq2  = (const float*)d_in[9];
    const float* bq2  = (const float*)d_in[10];
    const float* Wp2  = (const float*)d_in[11];
    const float* bp2  = (const float*)d_in[12];
    const float* a2   = (const float*)d_in[13];
    const float* b_out= (const float*)d_in[14];
    const int*   src  = (const int*)d_in[15];
    const int*   dst  = (const int*)d_in[16];

    float *q1, *p1, *q2, *p2;
    cudaGetSymbolAddress((void**)&q1, g_q1);
    cudaGetSymbolAddress((void**)&p1, g_p1);
    cudaGetSymbolAddress((void**)&q2, g_q2);
    cudaGetSymbolAddress((void**)&p2, g_p2);

    __nv_bfloat16 *xh, *xl, *m1h, *m1l, *m2h, *m2l;
    cudaGetSymbolAddress((void**)&xh, g_xh);
    cudaGetSymbolAddress((void**)&xl, g_xl);
    cudaGetSymbolAddress((void**)&m1h, g_m1h);
    cudaGetSymbolAddress((void**)&m1l, g_m1l);
    cudaGetSymbolAddress((void**)&m2h, g_m2h);
    cudaGetSymbolAddress((void**)&m2l, g_m2l);

    __nv_bfloat16 *w0h, *w0l, *wq1h, *wq1l, *wp1h, *wp1l, *wq2h, *wq2l, *wp2h, *wp2l;
    cudaGetSymbolAddress((void**)&w0h, g_w0h);
    cudaGetSymbolAddress((void**)&w0l, g_w0l);
    cudaGetSymbolAddress((void**)&wq1h, g_wq1h);
    cudaGetSymbolAddress((void**)&wq1l, g_wq1l);
    cudaGetSymbolAddress((void**)&wp1h, g_wp1h);
    cudaGetSymbolAddress((void**)&wp1l, g_wp1l);
    cudaGetSymbolAddress((void**)&wq2h, g_wq2h);
    cudaGetSymbolAddress((void**)&wq2l, g_wq2l);
    cudaGetSymbolAddress((void**)&wp2h, g_wp2h);
    cudaGetSymbolAddress((void**)&wp2l, g_wp2l);

    int* cntp;
    cudaGetSymbolAddress((void**)&cntp, g_cnt);

    const int gemm_gx = (N_NODES + 127) / 128;  // 391
    const dim3 qp_grid(gemm_gx, 2);
    const int gat_grid = (N_NODES + 7) / 8;     // 6250
    const int e4_grid = (N_EDGES / 4 + 255) / 256;

    // prep: split x + all weights (one launch)
    k_prep_all<<<(XN + 65536 + 255) / 256, 256>>>(x, W0, Wq1, Wp1, Wq2, Wp2);

    // CSR build
    cudaMemsetAsync(cntp, 0, N_NODES * sizeof(int));
    k_hist<<<e4_grid, 256>>>(dst);
    k_scan_part<<<SCAN_BLOCKS, 256>>>();
    k_scan_mid<<<1, 256>>>();
    k_scan_final<<<SCAN_BLOCKS, 256>>>();
    k_scatter<<<e4_grid, 256>>>(src, dst);

    // layer 1
    k_gemm<128, true, true><<<gemm_gx, 256>>>(xh, xl, w0h, w0l, b0, nullptr, m1h, m1l,
                                              w0h, w0l, b0, nullptr, N_NODES);
    k_gemm<128, false, false><<<qp_grid, 256>>>(m1h, m1l, wq1h, wq1l, bq1, q1, nullptr, nullptr,
                                                wp1h, wp1l, bp1, p1, N_NODES);
    k_gat128<<<gat_grid, 256>>>(q1, p1, a1, bg2, m2h, m2l);

    // layer 2
    k_gemm<64, false, false><<<qp_grid, 256>>>(m2h, m2l, wq2h, wq2l, bq2, q2, nullptr, nullptr,
                                               wp2h, wp2l, bp2, p2, N_NODES);
    k_gat64<<<gat_grid, 256>>>(q2, p2, a2, b_out, (float*)d_out);
}

// round 6
// speedup vs baseline: 1.9811x; 1.0378x over previous
#include <cuda_runtime.h>
#include <cuda_bf16.h>
#include <math.h>
#include <stdint.h>

#define N_NODES 50000
#define N_EDGES 800000
#define DH 128
#define DOUT 64
#define XN (N_NODES * DH)
#define SCAN_BLOCKS 196   // 196*256 = 50176 >= N_NODES

// ---------------- scratch (device globals) ----------------
__device__ __nv_bfloat16 g_xh[XN], g_xl[XN];
__device__ __nv_bfloat16 g_m1h[XN], g_m1l[XN];
__device__ __nv_bfloat16 g_m2h[XN], g_m2l[XN];
__device__ float g_q1[N_NODES * DH];
__device__ float g_p1[N_NODES * DH];
__device__ float g_q2[N_NODES * DOUT];
__device__ float g_p2[N_NODES * DOUT];
__device__ int   g_cnt[N_NODES];
__device__ int   g_fill[N_NODES];
__device__ int   g_rowptr[N_NODES + 1];
__device__ int   g_csrc[N_EDGES];
__device__ int   g_part[SCAN_BLOCKS];
__device__ int   g_partoff[SCAN_BLOCKS];

__device__ __nv_bfloat16 g_w0h[128 * 128], g_w0l[128 * 128];
__device__ __nv_bfloat16 g_wq1h[128 * 128], g_wq1l[128 * 128];
__device__ __nv_bfloat16 g_wp1h[128 * 128], g_wp1l[128 * 128];
__device__ __nv_bfloat16 g_wq2h[128 * 64], g_wq2l[128 * 64];
__device__ __nv_bfloat16 g_wp2h[128 * 64], g_wp2l[128 * 64];

// ---------------- helpers ----------------
__device__ __forceinline__ float gelu_erf(float x) {
    return 0.5f * x * (1.0f + erff(x * 0.70710678118654752440f));
}

__device__ __forceinline__ uint32_t smem_u32(const void* p) {
    uint32_t a;
    asm("{ .reg .u64 t; cvta.to.shared.u64 t, %1; cvt.u32.u64 %0, t; }" : "=r"(a) : "l"(p));
    return a;
}

__device__ __forceinline__ void ldx4(uint32_t* r, uint32_t addr) {
    asm volatile("ldmatrix.sync.aligned.m8n8.x4.shared.b16 {%0,%1,%2,%3}, [%4];"
                 : "=r"(r[0]), "=r"(r[1]), "=r"(r[2]), "=r"(r[3]) : "r"(addr));
}

__device__ __forceinline__ void ldx4t(uint32_t* r, uint32_t addr) {
    asm volatile("ldmatrix.sync.aligned.m8n8.x4.trans.shared.b16 {%0,%1,%2,%3}, [%4];"
                 : "=r"(r[0]), "=r"(r[1]), "=r"(r[2]), "=r"(r[3]) : "r"(addr));
}

__device__ __forceinline__ void mma16816(float* c, const uint32_t* a, uint32_t b0, uint32_t b1) {
    asm volatile(
        "mma.sync.aligned.m16n8k16.row.col.f32.bf16.bf16.f32 "
        "{%0,%1,%2,%3}, {%4,%5,%6,%7}, {%8,%9}, {%0,%1,%2,%3};"
        : "+f"(c[0]), "+f"(c[1]), "+f"(c[2]), "+f"(c[3])
        : "r"(a[0]), "r"(a[1]), "r"(a[2]), "r"(a[3]), "r"(b0), "r"(b1));
}

__device__ __forceinline__ void split2(float a, float b, uint32_t& hi, uint32_t& lo) {
    __nv_bfloat16 ha = __float2bfloat16(a), hb = __float2bfloat16(b);
    __nv_bfloat16 la = __float2bfloat16(a - __bfloat162float(ha));
    __nv_bfloat16 lb = __float2bfloat16(b - __bfloat162float(hb));
    hi = (uint32_t)__bfloat16_as_ushort(ha) | ((uint32_t)__bfloat16_as_ushort(hb) << 16);
    lo = (uint32_t)__bfloat16_as_ushort(la) | ((uint32_t)__bfloat16_as_ushort(lb) << 16);
}

#define LRELU(d) ((d) > 0.f ? (d) : 0.2f * (d))

// ---------------- merged prep ----------------
__global__ void k_prep_all(const float* __restrict__ x,
                           const float* __restrict__ W0, const float* __restrict__ Wq1,
                           const float* __restrict__ Wp1, const float* __restrict__ Wq2,
                           const float* __restrict__ Wp2) {
    int idx = blockIdx.x * blockDim.x + threadIdx.x;
    const float* srcp;
    __nv_bfloat16 *dh, *dl;
    int off;
    if (idx < XN) {
        srcp = x; dh = g_xh; dl = g_xl; off = idx;
    } else {
        int j = idx - XN;
        if (j < 16384)       { srcp = W0;  dh = g_w0h;  dl = g_w0l;  off = j; }
        else if (j < 32768)  { srcp = Wq1; dh = g_wq1h; dl = g_wq1l; off = j - 16384; }
        else if (j < 49152)  { srcp = Wp1; dh = g_wp1h; dl = g_wp1l; off = j - 32768; }
        else if (j < 57344)  { srcp = Wq2; dh = g_wq2h; dl = g_wq2l; off = j - 49152; }
        else if (j < 65536)  { srcp = Wp2; dh = g_wp2h; dl = g_wp2l; off = j - 57344; }
        else return;
    }
    float v = srcp[off];
    __nv_bfloat16 h = __float2bfloat16(v);
    dh[off] = h;
    dl[off] = __float2bfloat16(v - __bfloat162float(h));
}

// ---------------- CSR build ----------------
__global__ void k_hist(const int* __restrict__ dst) {
    int t = blockIdx.x * blockDim.x + threadIdx.x;
    if (t < N_EDGES / 4) {
        int4 d = ((const int4*)dst)[t];
        atomicAdd(&g_cnt[d.x], 1);
        atomicAdd(&g_cnt[d.y], 1);
        atomicAdd(&g_cnt[d.z], 1);
        atomicAdd(&g_cnt[d.w], 1);
    }
}

__global__ void k_scan_part() {
    __shared__ int sd[256];
    int i = blockIdx.x * 256 + threadIdx.x;
    int v = (i < N_NODES) ? g_cnt[i] : 0;
    sd[threadIdx.x] = v;
    __syncthreads();
#pragma unroll
    for (int off = 128; off; off >>= 1) {
        if (threadIdx.x < off) sd[threadIdx.x] += sd[threadIdx.x + off];
        __syncthreads();
    }
    if (threadIdx.x == 0) g_part[blockIdx.x] = sd[0];
}

__global__ void k_scan_mid() {
    __shared__ int sd[256];
    int t = threadIdx.x;
    int v = (t < SCAN_BLOCKS) ? g_part[t] : 0;
    sd[t] = v;
    __syncthreads();
#pragma unroll
    for (int off = 1; off < 256; off <<= 1) {
        int u = (t >= off) ? sd[t - off] : 0;
        __syncthreads();
        sd[t] += u;
        __syncthreads();
    }
    if (t < SCAN_BLOCKS) g_partoff[t] = sd[t] - v;  // exclusive
}

__global__ void k_scan_final() {
    __shared__ int sd[256];
    int i = blockIdx.x * 256 + threadIdx.x;
    int t = threadIdx.x;
    int v = (i < N_NODES) ? g_cnt[i] : 0;
    sd[t] = v;
    __syncthreads();
#pragma unroll
    for (int off = 1; off < 256; off <<= 1) {
        int u = (t >= off) ? sd[t - off] : 0;
        __syncthreads();
        sd[t] += u;
        __syncthreads();
    }
    if (i < N_NODES) {
        int excl = g_partoff[blockIdx.x] + sd[t] - v;
        g_rowptr[i] = excl;
        g_fill[i] = excl;
    }
    if (i == N_NODES - 1) g_rowptr[N_NODES] = N_EDGES;
}

__global__ void k_scatter(const int* __restrict__ src, const int* __restrict__ dst) {
    int t = blockIdx.x * blockDim.x + threadIdx.x;
    if (t < N_EDGES / 4) {
        int4 d = ((const int4*)dst)[t];
        int4 s = ((const int4*)src)[t];
        g_csrc[atomicAdd(&g_fill[d.x], 1)] = s.x;
        g_csrc[atomicAdd(&g_fill[d.y], 1)] = s.y;
        g_csrc[atomicAdd(&g_fill[d.z], 1)] = s.z;
        g_csrc[atomicAdd(&g_fill[d.w], 1)] = s.w;
    }
}

// ---------------- mma.sync GEMM ----------------
template <int NO, bool ACT, bool SPLITOUT>
__global__ __launch_bounds__(256, 2) void k_gemm(
    const __nv_bfloat16* __restrict__ Ah, const __nv_bfloat16* __restrict__ Al,
    const __nv_bfloat16* __restrict__ Wh0, const __nv_bfloat16* __restrict__ Wl0,
    const float* __restrict__ bias0, float* __restrict__ Cf0,
    __nv_bfloat16* __restrict__ Ch0, __nv_bfloat16* __restrict__ Cl0,
    const __nv_bfloat16* __restrict__ Wh1, const __nv_bfloat16* __restrict__ Wl1,
    const float* __restrict__ bias1, float* __restrict__ Cf1, int M) {
    constexpr int AP = 40;
    constexpr int WPAD = NO + 8;
    constexpr int NB = NO / 16;

    const __nv_bfloat16* Wh = blockIdx.y ? Wh1 : Wh0;
    const __nv_bfloat16* Wl = blockIdx.y ? Wl1 : Wl0;
    const float* bias = blockIdx.y ? bias1 : bias0;
    float* Cf = blockIdx.y ? Cf1 : Cf0;

    __shared__ alignas(16) __nv_bfloat16 sAh[128 * AP];
    __shared__ alignas(16) __nv_bfloat16 sAl[128 * AP];
    __shared__ alignas(16) __nv_bfloat16 sWh[32 * WPAD];
    __shared__ alignas(16) __nv_bfloat16 sWl[32 * WPAD];

    const int tid = threadIdx.x;
    const int wid = tid >> 5, lane = tid & 31;
    const int wm = wid & 3, wn = wid >> 2;
    const int row0 = blockIdx.x * 128;

    float acc[2][NB][4];
#pragma unroll
    for (int mb = 0; mb < 2; mb++)
#pragma unroll
        for (int nb = 0; nb < NB; nb++)
#pragma unroll
            for (int j = 0; j < 4; j++) acc[mb][nb][j] = 0.f;

    const uint32_t aBaseH = smem_u32(sAh), aBaseL = smem_u32(sAl);
    const uint32_t wBaseH = smem_u32(sWh), wBaseL = smem_u32(sWl);

    const int a_row = wm * 32 + (lane & 15);
    const int a_col = (lane >> 4) * 8;
    const int b_blk = lane >> 3;
    const int b_rowoff = (b_blk & 1) * 8 + (lane & 7);
    const int b_coladd = wn * (NO / 2) + (b_blk >> 1) * 8;

    const uint4 z4 = make_uint4(0, 0, 0, 0);

    for (int c = 0; c < 4; c++) {
        const int k0 = c * 32;
        for (int i = tid; i < 512; i += 256) {
            int r = i >> 2, qq = i & 3;
            int grow = row0 + r;
            uint4 vh = z4, vl = z4;
            if (grow < M) {
                vh = *(const uint4*)(Ah + (size_t)grow * 128 + k0 + qq * 8);
                vl = *(const uint4*)(Al + (size_t)grow * 128 + k0 + qq * 8);
            }
            *(uint4*)(sAh + r * AP + qq * 8) = vh;
            *(uint4*)(sAl + r * AP + qq * 8) = vl;
        }
        for (int i = tid; i < 32 * NO / 8; i += 256) {
            int r = i / (NO / 8), off = (i % (NO / 8)) * 8;
            *(uint4*)(sWh + r * WPAD + off) = *(const uint4*)(Wh + (size_t)(k0 + r) * NO + off);
            *(uint4*)(sWl + r * WPAD + off) = *(const uint4*)(Wl + (size_t)(k0 + r) * NO + off);
        }
        __syncthreads();

#pragma unroll
        for (int kc = 0; kc < 32; kc += 16) {
            uint32_t ah[2][4], al[2][4];
#pragma unroll
            for (int mb = 0; mb < 2; mb++) {
                uint32_t off = (uint32_t)((a_row + mb * 16) * AP + kc + a_col) * 2;
                ldx4(ah[mb], aBaseH + off);
                ldx4(al[mb], aBaseL + off);
            }
#pragma unroll
            for (int nb = 0; nb < NB; nb += 2) {
                uint32_t bh[4], bl[4];
                uint32_t off = (uint32_t)((kc + b_rowoff) * WPAD + nb * 8 + b_coladd) * 2;
                ldx4t(bh, wBaseH + off);
                ldx4t(bl, wBaseL + off);
#pragma unroll
                for (int mb = 0; mb < 2; mb++) {
                    mma16816(acc[mb][nb], ah[mb], bh[0], bh[1]);
                    mma16816(acc[mb][nb + 1], ah[mb], bh[2], bh[3]);
                    mma16816(acc[mb][nb], ah[mb], bl[0], bl[1]);
                    mma16816(acc[mb][nb + 1], ah[mb], bl[2], bl[3]);
                    mma16816(acc[mb][nb], al[mb], bh[0], bh[1]);
                    mma16816(acc[mb][nb + 1], al[mb], bh[2], bh[3]);
                }
            }
        }
        __syncthreads();
    }

#pragma unroll
    for (int mb = 0; mb < 2; mb++) {
#pragma unroll
        for (int nb = 0; nb < NB; nb++) {
            int col = wn * (NO / 2) + nb * 8 + (lane & 3) * 2;
            float b0 = bias[col], b1 = bias[col + 1];
#pragma unroll
            for (int half = 0; half < 2; half++) {
                int r = row0 + wm * 32 + mb * 16 + (lane >> 2) + half * 8;
                if (r < M) {
                    float o0 = acc[mb][nb][half * 2 + 0] + b0;
                    float o1 = acc[mb][nb][half * 2 + 1] + b1;
                    if (ACT) { o0 = gelu_erf(o0); o1 = gelu_erf(o1); }
                    if (SPLITOUT) {
                        uint32_t hi, lo;
                        split2(o0, o1, hi, lo);
                        *(uint32_t*)(Ch0 + (size_t)r * NO + col) = hi;
                        *(uint32_t*)(Cl0 + (size_t)r * NO + col) = lo;
                    } else {
                        *(float2*)(Cf + (size_t)r * NO + col) = make_float2(o0, o1);
                    }
                }
            }
        }
    }
}

// ---------------- GAT D=128: half-warp edge streams, 4-edge ILP unroll ----------
__global__ __launch_bounds__(256) void k_gat128(const float* __restrict__ q,
                                                const float* __restrict__ p,
                                                const float* __restrict__ avec,
                                                const float* __restrict__ badd,
                                                __nv_bfloat16* __restrict__ outh,
                                                __nv_bfloat16* __restrict__ outl) {
    int w = (blockIdx.x * blockDim.x + threadIdx.x) >> 5;
    int lane = threadIdx.x & 31;
    if (w >= N_NODES) return;
    int half = lane >> 4, hl = lane & 15;

    const float4* q4 = (const float4*)q;
    const float4* p4 = (const float4*)p;
    const float4* a4 = (const float4*)avec;
    float4 qv0 = q4[(size_t)w * 32 + hl * 2];
    float4 qv1 = q4[(size_t)w * 32 + hl * 2 + 1];
    float4 av0 = a4[hl * 2], av1 = a4[hl * 2 + 1];

    int beg = g_rowptr[w];
    int count = g_rowptr[w + 1] - beg;
    int n0 = (count + 1) >> 1;
    int base = beg + half * n0;
    int cnt_h = half ? (count - n0) : n0;

    float denom = 0.f;
    float s0 = 0.f, s1 = 0.f, s2 = 0.f, s3 = 0.f;
    float s4 = 0.f, s5 = 0.f, s6 = 0.f, s7 = 0.f;

    for (int it = 0; it < n0; it += 4) {
        bool act0 = it < cnt_h, act1 = it + 1 < cnt_h;
        bool act2 = it + 2 < cnt_h, act3 = it + 3 < cnt_h;
        int i0 = act0 ? g_csrc[base + it] : 0;
        int i1 = act1 ? g_csrc[base + it + 1] : 0;
        int i2 = act2 ? g_csrc[base + it + 2] : 0;
        int i3 = act3 ? g_csrc[base + it + 3] : 0;
        float4 pA0 = p4[(size_t)i0 * 32 + hl * 2];
        float4 pA1 = p4[(size_t)i0 * 32 + hl * 2 + 1];
        float4 pB0 = p4[(size_t)i1 * 32 + hl * 2];
        float4 pB1 = p4[(size_t)i1 * 32 + hl * 2 + 1];
        float4 pC0 = p4[(size_t)i2 * 32 + hl * 2];
        float4 pC1 = p4[(size_t)i2 * 32 + hl * 2 + 1];
        float4 pD0 = p4[(size_t)i3 * 32 + hl * 2];
        float4 pD1 = p4[(size_t)i3 * 32 + hl * 2 + 1];

        float pa = LRELU(qv0.x + pA0.x) * av0.x + LRELU(qv0.y + pA0.y) * av0.y +
                   LRELU(qv0.z + pA0.z) * av0.z + LRELU(qv0.w + pA0.w) * av0.w +
                   LRELU(qv1.x + pA1.x) * av1.x + LRELU(qv1.y + pA1.y) * av1.y +
                   LRELU(qv1.z + pA1.z) * av1.z + LRELU(qv1.w + pA1.w) * av1.w;
        float pb = LRELU(qv0.x + pB0.x) * av0.x + LRELU(qv0.y + pB0.y) * av0.y +
                   LRELU(qv0.z + pB0.z) * av0.z + LRELU(qv0.w + pB0.w) * av0.w +
                   LRELU(qv1.x + pB1.x) * av1.x + LRELU(qv1.y + pB1.y) * av1.y +
                   LRELU(qv1.z + pB1.z) * av1.z + LRELU(qv1.w + pB1.w) * av1.w;
        float pc = LRELU(qv0.x + pC0.x) * av0.x + LRELU(qv0.y + pC0.y) * av0.y +
                   LRELU(qv0.z + pC0.z) * av0.z + LRELU(qv0.w + pC0.w) * av0.w +
                   LRELU(qv1.x + pC1.x) * av1.x + LRELU(qv1.y + pC1.y) * av1.y +
                   LRELU(qv1.z + pC1.z) * av1.z + LRELU(qv1.w + pC1.w) * av1.w;
        float pd = LRELU(qv0.x + pD0.x) * av0.x + LRELU(qv0.y + pD0.y) * av0.y +
                   LRELU(qv0.z + pD0.z) * av0.z + LRELU(qv0.w + pD0.w) * av0.w +
                   LRELU(qv1.x + pD1.x) * av1.x + LRELU(qv1.y + pD1.y) * av1.y +
                   LRELU(qv1.z + pD1.z) * av1.z + LRELU(qv1.w + pD1.w) * av1.w;

#pragma unroll
        for (int o = 8; o; o >>= 1) {
            pa += __shfl_xor_sync(0xffffffffu, pa, o);
            pb += __shfl_xor_sync(0xffffffffu, pb, o);
            pc += __shfl_xor_sync(0xffffffffu, pc, o);
            pd += __shfl_xor_sync(0xffffffffu, pd, o);
        }
        float eA = act0 ? __expf(pa) : 0.f;
        float eB = act1 ? __expf(pb) : 0.f;
        float eC = act2 ? __expf(pc) : 0.f;
        float eD = act3 ? __expf(pd) : 0.f;
        denom += (eA + eB) + (eC + eD);
        s0 = fmaf(eA, pA0.x, fmaf(eB, pB0.x, fmaf(eC, pC0.x, fmaf(eD, pD0.x, s0))));
        s1 = fmaf(eA, pA0.y, fmaf(eB, pB0.y, fmaf(eC, pC0.y, fmaf(eD, pD0.y, s1))));
        s2 = fmaf(eA, pA0.z, fmaf(eB, pB0.z, fmaf(eC, pC0.z, fmaf(eD, pD0.z, s2))));
        s3 = fmaf(eA, pA0.w, fmaf(eB, pB0.w, fmaf(eC, pC0.w, fmaf(eD, pD0.w, s3))));
        s4 = fmaf(eA, pA1.x, fmaf(eB, pB1.x, fmaf(eC, pC1.x, fmaf(eD, pD1.x, s4))));
        s5 = fmaf(eA, pA1.y, fmaf(eB, pB1.y, fmaf(eC, pC1.y, fmaf(eD, pD1.y, s5))));
        s6 = fmaf(eA, pA1.z, fmaf(eB, pB1.z, fmaf(eC, pC1.z, fmaf(eD, pD1.z, s6))));
        s7 = fmaf(eA, pA1.w, fmaf(eB, pB1.w, fmaf(eC, pC1.w, fmaf(eD, pD1.w, s7))));
    }
    denom += __shfl_xor_sync(0xffffffffu, denom, 16);
    s0 += __shfl_xor_sync(0xffffffffu, s0, 16);
    s1 += __shfl_xor_sync(0xffffffffu, s1, 16);
    s2 += __shfl_xor_sync(0xffffffffu, s2, 16);
    s3 += __shfl_xor_sync(0xffffffffu, s3, 16);
    s4 += __shfl_xor_sync(0xffffffffu, s4, 16);
    s5 += __shfl_xor_sync(0xffffffffu, s5, 16);
    s6 += __shfl_xor_sync(0xffffffffu, s6, 16);
    s7 += __shfl_xor_sync(0xffffffffu, s7, 16);

    if (half == 0) {
        float inv = (count > 0) ? 1.f / denom : 0.f;
        int col = hl * 8;
        float v0 = gelu_erf(fmaf(s0, inv, badd[col + 0]));
        float v1 = gelu_erf(fmaf(s1, inv, badd[col + 1]));
        float v2 = gelu_erf(fmaf(s2, inv, badd[col + 2]));
        float v3 = gelu_erf(fmaf(s3, inv, badd[col + 3]));
        float v4 = gelu_erf(fmaf(s4, inv, badd[col + 4]));
        float v5 = gelu_erf(fmaf(s5, inv, badd[col + 5]));
        float v6 = gelu_erf(fmaf(s6, inv, badd[col + 6]));
        float v7 = gelu_erf(fmaf(s7, inv, badd[col + 7]));
        uint32_t h01, l01, h23, l23, h45, l45, h67, l67;
        split2(v0, v1, h01, l01);
        split2(v2, v3, h23, l23);
        split2(v4, v5, h45, l45);
        split2(v6, v7, h67, l67);
        *(uint4*)(outh + (size_t)w * 128 + col) = make_uint4(h01, h23, h45, h67);
        *(uint4*)(outl + (size_t)w * 128 + col) = make_uint4(l01, l23, l45, l67);
    }
}

// ---------------- GAT D=64: half-warp edge streams, 4-edge ILP unroll -----------
__global__ __launch_bounds__(256) void k_gat64(const float* __restrict__ q,
                                               const float* __restrict__ p,
                                               const float* __restrict__ avec,
                                               const float* __restrict__ bout,
                                               float* __restrict__ out) {
    int w = (blockIdx.x * blockDim.x + threadIdx.x) >> 5;
    int lane = threadIdx.x & 31;
    if (w >= N_NODES) return;
    int half = lane >> 4, hl = lane & 15;

    const float4* q4 = (const float4*)q;
    const float4* p4 = (const float4*)p;
    float4 qv = q4[(size_t)w * 16 + hl];
    float4 av = ((const float4*)avec)[hl];

    int beg = g_rowptr[w];
    int count = g_rowptr[w + 1] - beg;
    int n0 = (count + 1) >> 1;
    int base = beg + half * n0;
    int cnt_h = half ? (count - n0) : n0;

    float denom = 0.f;
    float s0 = 0.f, s1 = 0.f, s2 = 0.f, s3 = 0.f;

    for (int it = 0; it < n0; it += 4) {
        bool act0 = it < cnt_h, act1 = it + 1 < cnt_h;
        bool act2 = it + 2 < cnt_h, act3 = it + 3 < cnt_h;
        int i0 = act0 ? g_csrc[base + it] : 0;
        int i1 = act1 ? g_csrc[base + it + 1] : 0;
        int i2 = act2 ? g_csrc[base + it + 2] : 0;
        int i3 = act3 ? g_csrc[base + it + 3] : 0;
        float4 pA = p4[(size_t)i0 * 16 + hl];
        float4 pB = p4[(size_t)i1 * 16 + hl];
        float4 pC = p4[(size_t)i2 * 16 + hl];
        float4 pD = p4[(size_t)i3 * 16 + hl];

        float pa = LRELU(qv.x + pA.x) * av.x + LRELU(qv.y + pA.y) * av.y +
                   LRELU(qv.z + pA.z) * av.z + LRELU(qv.w + pA.w) * av.w;
        float pb = LRELU(qv.x + pB.x) * av.x + LRELU(qv.y + pB.y) * av.y +
                   LRELU(qv.z + pB.z) * av.z + LRELU(qv.w + pB.w) * av.w;
        float pc = LRELU(qv.x + pC.x) * av.x + LRELU(qv.y + pC.y) * av.y +
                   LRELU(qv.z + pC.z) * av.z + LRELU(qv.w + pC.w) * av.w;
        float pd = LRELU(qv.x + pD.x) * av.x + LRELU(qv.y + pD.y) * av.y +
                   LRELU(qv.z + pD.z) * av.z + LRELU(qv.w + pD.w) * av.w;

#pragma unroll
        for (int o = 8; o; o >>= 1) {
            pa += __shfl_xor_sync(0xffffffffu, pa, o);
            pb += __shfl_xor_sync(0xffffffffu, pb, o);
            pc += __shfl_xor_sync(0xffffffffu, pc, o);
            pd += __shfl_xor_sync(0xffffffffu, pd, o);
        }
        float eA = act0 ? __expf(pa) : 0.f;
        float eB = act1 ? __expf(pb) : 0.f;
        float eC = act2 ? __expf(pc) : 0.f;
        float eD = act3 ? __expf(pd) : 0.f;
        denom += (eA + eB) + (eC + eD);
        s0 = fmaf(eA, pA.x, fmaf(eB, pB.x, fmaf(eC, pC.x, fmaf(eD, pD.x, s0))));
        s1 = fmaf(eA, pA.y, fmaf(eB, pB.y, fmaf(eC, pC.y, fmaf(eD, pD.y, s1))));
        s2 = fmaf(eA, pA.z, fmaf(eB, pB.z, fmaf(eC, pC.z, fmaf(eD, pD.z, s2))));
        s3 = fmaf(eA, pA.w, fmaf(eB, pB.w, fmaf(eC, pC.w, fmaf(eD, pD.w, s3))));
    }
    denom += __shfl_xor_sync(0xffffffffu, denom, 16);
    s0 += __shfl_xor_sync(0xffffffffu, s0, 16);
    s1 += __shfl_xor_sync(0xffffffffu, s1, 16);
    s2 += __shfl_xor_sync(0xffffffffu, s2, 16);
    s3 += __shfl_xor_sync(0xffffffffu, s3, 16);

    if (half == 0) {
        float inv = (count > 0) ? 1.f / denom : 0.f;
        int col = hl * 4;
        float4 o;
        o.x = fmaf(s0, inv, bout[col + 0]);
        o.y = fmaf(s1, inv, bout[col + 1]);
        o.z = fmaf(s2, inv, bout[col + 2]);
        o.w = fmaf(s3, inv, bout[col + 3]);
        ((float4*)out)[(size_t)w * 16 + hl] = o;
    }
}

// ---------------- launch ----------------
extern "C" void kernel_launch(void* const* d_in, const int* in_sizes, int n_in,
                              void* d_out, int out_size) {
    const float* x    = (const float*)d_in[0];
    const float* W0   = (const float*)d_in[1];
    const float* b0   = (const float*)d_in[2];
    const float* Wq1  = (const float*)d_in[3];
    const float* bq1  = (const float*)d_in[4];
    const float* Wp1  = (const float*)d_in[5];
    const float* bp1  = (const float*)d_in[6];
    const float* a1   = (const float*)d_in[7];
    const float* bg2  = (const float*)d_in[8];
    const float* Wq2  = (const float*)d_in[9];
    const float* bq2  = (const float*)d_in[10];
    const float* Wp2  = (const float*)d_in[11];
    const float* bp2  = (const float*)d_in[12];
    const float* a2   = (const float*)d_in[13];
    const float* b_out= (const float*)d_in[14];
    const int*   src  = (const int*)d_in[15];
    const int*   dst  = (const int*)d_in[16];

    float *q1, *p1, *q2, *p2;
    cudaGetSymbolAddress((void**)&q1, g_q1);
    cudaGetSymbolAddress((void**)&p1, g_p1);
    cudaGetSymbolAddress((void**)&q2, g_q2);
    cudaGetSymbolAddress((void**)&p2, g_p2);

    __nv_bfloat16 *xh, *xl, *m1h, *m1l, *m2h, *m2l;
    cudaGetSymbolAddress((void**)&xh, g_xh);
    cudaGetSymbolAddress((void**)&xl, g_xl);
    cudaGetSymbolAddress((void**)&m1h, g_m1h);
    cudaGetSymbolAddress((void**)&m1l, g_m1l);
    cudaGetSymbolAddress((void**)&m2h, g_m2h);
    cudaGetSymbolAddress((void**)&m2l, g_m2l);

    __nv_bfloat16 *w0h, *w0l, *wq1h, *wq1l, *wp1h, *wp1l, *wq2h, *wq2l, *wp2h, *wp2l;
    cudaGetSymbolAddress((void**)&w0h, g_w0h);
    cudaGetSymbolAddress((void**)&w0l, g_w0l);
    cudaGetSymbolAddress((void**)&wq1h, g_wq1h);
    cudaGetSymbolAddress((void**)&wq1l, g_wq1l);
    cudaGetSymbolAddress((void**)&wp1h, g_wp1h);
    cudaGetSymbolAddress((void**)&wp1l, g_wp1l);
    cudaGetSymbolAddress((void**)&wq2h, g_wq2h);
    cudaGetSymbolAddress((void**)&wq2l, g_wq2l);
    cudaGetSymbolAddress((void**)&wp2h, g_wp2h);
    cudaGetSymbolAddress((void**)&wp2l, g_wp2l);

    int* cntp;
    cudaGetSymbolAddress((void**)&cntp, g_cnt);

    const int gemm_gx = (N_NODES + 127) / 128;  // 391
    const dim3 qp_grid(gemm_gx, 2);
    const int gat_grid = (N_NODES + 7) / 8;     // 6250
    const int e4_grid = (N_EDGES / 4 + 255) / 256;

    // side stream for CSR build (overlaps with prep + layer-1 GEMMs)
    cudaStream_t s2;
    cudaStreamCreateWithFlags(&s2, cudaStreamNonBlocking);
    cudaEvent_t eFork, eJoin;
    cudaEventCreateWithFlags(&eFork, cudaEventDisableTiming);
    cudaEventCreateWithFlags(&eJoin, cudaEventDisableTiming);

    // fork
    cudaEventRecord(eFork, 0);
    cudaStreamWaitEvent(s2, eFork, 0);

    // CSR build on s2
    cudaMemsetAsync(cntp, 0, N_NODES * sizeof(int), s2);
    k_hist<<<e4_grid, 256, 0, s2>>>(dst);
    k_scan_part<<<SCAN_BLOCKS, 256, 0, s2>>>();
    k_scan_mid<<<1, 256, 0, s2>>>();
    k_scan_final<<<SCAN_BLOCKS, 256, 0, s2>>>();
    k_scatter<<<e4_grid, 256, 0, s2>>>(src, dst);
    cudaEventRecord(eJoin, s2);

    // main chain on capture stream
    k_prep_all<<<(XN + 65536 + 255) / 256, 256>>>(x, W0, Wq1, Wp1, Wq2, Wp2);
    k_gemm<128, true, true><<<gemm_gx, 256>>>(xh, xl, w0h, w0l, b0, nullptr, m1h, m1l,
                                              w0h, w0l, b0, nullptr, N_NODES);
    k_gemm<128, false, false><<<qp_grid, 256>>>(m1h, m1l, wq1h, wq1l, bq1, q1, nullptr, nullptr,
                                                wp1h, wp1l, bp1, p1, N_NODES);

    // join: gat128 needs CSR
    cudaStreamWaitEvent(0, eJoin, 0);
    k_gat128<<<gat_grid, 256>>>(q1, p1, a1, bg2, m2h, m2l);

    k_gemm<64, false, false><<<qp_grid, 256>>>(m2h, m2l, wq2h, wq2l, bq2, q2, nullptr, nullptr,
                                               wp2h, wp2l, bp2, p2, N_NODES);
    k_gat64<<<gat_grid, 256>>>(q2, p2, a2, b_out, (float*)d_out);

    cudaEventDestroy(eFork);
    cudaEventDestroy(eJoin);
    cudaStreamDestroy(s2);
}